// round 12
// baseline (speedup 1.0000x reference)
#include <cuda_runtime.h>
#include <cuda_fp16.h>
#include <cstdint>
#include <cstddef>

#define N_NODES 100000
#define N_EDGES 1600000
#define IN_CH   256
#define HID     128
#define OUT_CH  64
#define NB_SCAN ((N_NODES + 1023) / 1024)   // 98

// ---------------- scratch (no allocs allowed) ----------------
__device__ int    g_cnt[N_NODES];           // zero at load; re-zeroed by agg2 tail each call
__device__ int    g_rowptr[N_NODES + 1];
__device__ int    g_part[128];
__device__ int    g_col[N_EDGES];
__device__ float  g_dinv[N_NODES];
__device__ float  g_wt1[HID * IN_CH];       // W1^T, tf32-rounded
__device__ __half g_wt2h[OUT_CH * HID];     // W2^T, fp16
__device__ __half g_xw[(size_t)N_NODES * HID];     // x @ W1, fp16
__device__ __half g_hw[(size_t)N_NODES * OUT_CH];  // h @ W2, fp16

// ---------------- small PTX helpers ----------------
__device__ __forceinline__ uint32_t smem_u32(const void* p) {
    return (uint32_t)__cvta_generic_to_shared(p);
}
__device__ __forceinline__ void cp16(uint32_t dst, const void* src, bool pred) {
    asm volatile("cp.async.cg.shared.global [%0], [%1], 16, %2;"
                 :: "r"(dst), "l"(src), "r"(pred ? 16 : 0));
}
__device__ __forceinline__ void cp_commit() { asm volatile("cp.async.commit_group;"); }
template <int N>
__device__ __forceinline__ void cp_wait() { asm volatile("cp.async.wait_group %0;" :: "n"(N)); }

__device__ __forceinline__ void ldsm4(uint32_t& r0, uint32_t& r1, uint32_t& r2, uint32_t& r3,
                                      uint32_t addr) {
    asm volatile("ldmatrix.sync.aligned.m8n8.x4.b16 {%0,%1,%2,%3}, [%4];"
                 : "=r"(r0), "=r"(r1), "=r"(r2), "=r"(r3) : "r"(addr));
}
__device__ __forceinline__ void mma_tf32(float* c, const uint32_t* a, const uint32_t* b) {
    asm volatile("mma.sync.aligned.m16n8k8.row.col.f32.tf32.tf32.f32 "
                 "{%0,%1,%2,%3}, {%4,%5,%6,%7}, {%8,%9}, {%0,%1,%2,%3};"
                 : "+f"(c[0]), "+f"(c[1]), "+f"(c[2]), "+f"(c[3])
                 : "r"(a[0]), "r"(a[1]), "r"(a[2]), "r"(a[3]), "r"(b[0]), "r"(b[1]));
}
__device__ __forceinline__ void mma_f16(float* c, const uint32_t* a, const uint32_t* b) {
    asm volatile("mma.sync.aligned.m16n8k16.row.col.f32.f16.f16.f32 "
                 "{%0,%1,%2,%3}, {%4,%5,%6,%7}, {%8,%9}, {%0,%1,%2,%3};"
                 : "+f"(c[0]), "+f"(c[1]), "+f"(c[2]), "+f"(c[3])
                 : "r"(a[0]), "r"(a[1]), "r"(a[2]), "r"(a[3]), "r"(b[0]), "r"(b[1]));
}
__device__ __forceinline__ uint32_t to_tf32(uint32_t x) {
    float f = __uint_as_float(x);
    uint32_t o;
    asm("cvt.rna.tf32.f32 %0, %1;" : "=r"(o) : "f"(f));
    return o;
}
__device__ __forceinline__ float round_tf32_f(float f) {
    uint32_t o;
    asm("cvt.rna.tf32.f32 %0, %1;" : "=r"(o) : "f"(f));
    return __uint_as_float(o);
}
__device__ __forceinline__ void h2acc(float* acc, uint32_t u0, float d) {
    float2 f = __half22float2(*(const __half2*)&u0);
    acc[0] += f.x * d; acc[1] += f.y * d;
}

// ---------------- weight transpose/round (gemm-stream) ----------------
__global__ void k_prep_w(const float* __restrict__ W1, const float* __restrict__ W2) {
    int i = blockIdx.x * blockDim.x + threadIdx.x;
    if (i < IN_CH * HID) {             // W1 [256][128] -> Wt1 [128][256], tf32
        int k = i / HID, n = i % HID;
        g_wt1[n * IN_CH + k] = round_tf32_f(W1[i]);
    }
    if (i < HID * OUT_CH) {            // W2 [128][64] -> Wt2h [64][128], fp16
        int k = i / OUT_CH, n = i % OUT_CH;
        g_wt2h[n * HID + k] = __float2half_rn(W2[i]);
    }
}

// ---------------- degree / CSR build (graph-stream) ----------------
__global__ void k_hist(const int* __restrict__ ei) {
    int e = blockIdx.x * blockDim.x + threadIdx.x;
    if (e < N_EDGES) atomicAdd(&g_cnt[ei[N_EDGES + e]], 1);
}

__global__ void k_scan1() {
    __shared__ int warpsum[32];
    int i = blockIdx.x * 1024 + threadIdx.x;
    int lane = threadIdx.x & 31, wid = threadIdx.x >> 5;
    int c = (i < N_NODES) ? g_cnt[i] : 0;
    if (i < N_NODES) g_dinv[i] = rsqrtf((float)c + 1.0f);  // +1 self loop
    int x = c;
    #pragma unroll
    for (int d = 1; d < 32; d <<= 1) {
        int y = __shfl_up_sync(0xFFFFFFFFu, x, d);
        if (lane >= d) x += y;
    }
    if (lane == 31) warpsum[wid] = x;
    __syncthreads();
    if (wid == 0) {
        int s = warpsum[lane];
        #pragma unroll
        for (int d = 1; d < 32; d <<= 1) {
            int y = __shfl_up_sync(0xFFFFFFFFu, s, d);
            if (lane >= d) s += y;
        }
        warpsum[lane] = s;
    }
    __syncthreads();
    int incl = x + (wid > 0 ? warpsum[wid - 1] : 0);
    if (i < N_NODES) g_rowptr[i + 1] = incl;
    if (threadIdx.x == 1023) g_part[blockIdx.x] = incl;
}

// fused scan2+scan3: every block redundantly scans the 98 partials in smem
__global__ void k_scan23() {
    __shared__ int parts[128];
    int tid = threadIdx.x;
    if (tid < 128) parts[tid] = (tid < NB_SCAN) ? g_part[tid] : 0;
    __syncthreads();
    #pragma unroll
    for (int d = 1; d < 128; d <<= 1) {
        int t = (tid < 128 && tid >= d) ? parts[tid - d] : 0;
        __syncthreads();
        if (tid < 128) parts[tid] += t;
        __syncthreads();
    }
    int base = (blockIdx.x > 0) ? parts[blockIdx.x - 1] : 0;  // exclusive prefix
    int i = blockIdx.x * 1024 + tid;
    if (i < N_NODES) {
        g_rowptr[i + 1] += base;
        g_cnt[i] = 0;  // reset for fill
    }
    if (i == 0) g_rowptr[0] = 0;
}

__global__ void k_fill(const int* __restrict__ ei) {
    int e = blockIdx.x * blockDim.x + threadIdx.x;
    if (e < N_EDGES) {
        int src = ei[e];
        int dst = ei[N_EDGES + e];
        int pos = g_rowptr[dst] + atomicAdd(&g_cnt[dst], 1);
        g_col[pos] = src;
    }
}

// ---------------- tf32 tensor-core GEMM1: C[M,128] = A[M,256] @ Wt1^T, fp16 out ----------------
template <int BN, int KDIM>
__global__ void __launch_bounds__(256) k_gemm(const float* __restrict__ A,
                                              const float* __restrict__ Wt,
                                              __half* __restrict__ C, int M) {
    constexpr int BM = 128, BK = 16;
    constexpr int NK = KDIM / BK;
    constexpr int LDSW = 20;             // 16 + 4 pad -> conflict-free ldmatrix
    constexpr int N_TILES = BN / 16;
    __shared__ float As[2][BM][LDSW];
    __shared__ float Bs[2][BN][LDSW];

    const int tid = threadIdx.x;
    const int lane = tid & 31, wid = tid >> 5;
    const int wm = (wid & 3) * 32;
    const int wn = (wid >> 2) * (BN / 2);
    const int m0 = blockIdx.x * BM;

    float acc[2][N_TILES][4];
    #pragma unroll
    for (int mt = 0; mt < 2; mt++)
        #pragma unroll
        for (int nt = 0; nt < N_TILES; nt++)
            #pragma unroll
            for (int r = 0; r < 4; r++) acc[mt][nt][r] = 0.f;

    #define LOAD_TILE(T, BUF)                                                        \
    {                                                                                \
        const int k0_ = (T) * BK;                                                    \
        _Pragma("unroll")                                                            \
        for (int l = 0; l < 2; l++) {                                                \
            int q = tid + l * 256;                                                   \
            int row = q >> 2, kq = q & 3;                                            \
            cp16(smem_u32(&As[BUF][row][kq * 4]),                                    \
                 A + (size_t)(m0 + row) * KDIM + k0_ + kq * 4, (m0 + row) < M);      \
        }                                                                            \
        _Pragma("unroll")                                                            \
        for (int l = 0; l < BN / 64; l++) {                                          \
            int q = tid + l * 256;                                                   \
            int n = q >> 2, kq = q & 3;                                              \
            cp16(smem_u32(&Bs[BUF][n][kq * 4]),                                      \
                 Wt + (size_t)n * KDIM + k0_ + kq * 4, true);                        \
        }                                                                            \
        cp_commit();                                                                 \
    }

    LOAD_TILE(0, 0);
    int buf = 0;
    for (int t = 0; t < NK; t++) {
        if (t + 1 < NK) { LOAD_TILE(t + 1, buf ^ 1); cp_wait<1>(); }
        else            { cp_wait<0>(); }
        __syncthreads();

        #pragma unroll
        for (int ks = 0; ks < 2; ks++) {
            const int kb = ks * 8;
            uint32_t a[2][4];
            #pragma unroll
            for (int mt = 0; mt < 2; mt++) {
                int row = wm + mt * 16 + (lane & 15);
                int col = kb + ((lane & 16) >> 2);
                ldsm4(a[mt][0], a[mt][1], a[mt][2], a[mt][3],
                      smem_u32(&As[buf][row][col]));
                #pragma unroll
                for (int r = 0; r < 4; r++) a[mt][r] = to_tf32(a[mt][r]);
            }
            uint32_t b[N_TILES][2];
            #pragma unroll
            for (int np = 0; np < N_TILES / 2; np++) {
                int row = wn + np * 16 + (lane & 7) + ((lane & 16) >> 1);
                int col = kb + ((lane & 8) >> 1);
                uint32_t r0, r1, r2, r3;
                ldsm4(r0, r1, r2, r3, smem_u32(&Bs[buf][row][col]));
                b[2 * np][0] = r0; b[2 * np][1] = r1;
                b[2 * np + 1][0] = r2; b[2 * np + 1][1] = r3;
            }
            #pragma unroll
            for (int mt = 0; mt < 2; mt++)
                #pragma unroll
                for (int nt = 0; nt < N_TILES; nt++)
                    mma_tf32(acc[mt][nt], a[mt], b[nt]);
        }
        __syncthreads();
        buf ^= 1;
    }
    #undef LOAD_TILE

    #pragma unroll
    for (int mt = 0; mt < 2; mt++) {
        int r0 = m0 + wm + mt * 16 + (lane >> 2);
        #pragma unroll
        for (int nt = 0; nt < N_TILES; nt++) {
            int cix = wn + nt * 8 + (lane & 3) * 2;
            if (r0 < M)
                *(__half2*)&C[(size_t)r0 * BN + cix] =
                    __floats2half2_rn(acc[mt][nt][0], acc[mt][nt][1]);
            if (r0 + 8 < M)
                *(__half2*)&C[(size_t)(r0 + 8) * BN + cix] =
                    __floats2half2_rn(acc[mt][nt][2], acc[mt][nt][3]);
        }
    }
}

// ---------------- fused agg1 + gemm2: per block, aggregate 128 nodes into smem
// then compute hw[128,64] = h_tile[128,128] @ Wt2h^T.  512 threads, 16 warps. ----------------
#define PITCH 136   // halves; 272B row = odd multiple of 16B -> conflict-free ldmatrix

__global__ void __launch_bounds__(512, 2) k_fused2(const float* __restrict__ b1,
                                                   const __half* __restrict__ Wt,
                                                   __half* __restrict__ C) {
    extern __shared__ __half sh[];
    __half* As = sh;                   // [128][PITCH]
    __half* Bs = sh + 128 * PITCH;     // [64][PITCH]

    const int tid = threadIdx.x;
    const int lane = tid & 31, wid = tid >> 5;
    const int m0 = blockIdx.x * 128;

    // kick off B load: 64 rows x 128 halves = 1024 cp16, 2 per thread
    // (R10 bug: only half of B was loaded -> NaN. Now each thread copies 16 halves.)
    {
        int row = tid >> 3;            // 0..63
        int co  = (tid & 7) * 16;      // 0,16,...,112
        cp16(smem_u32(&Bs[row * PITCH + co]),     Wt + row * HID + co,     true);
        cp16(smem_u32(&Bs[row * PITCH + co + 8]), Wt + row * HID + co + 8, true);
        cp_commit();
    }

    // ---- phase 1: each warp aggregates 8 nodes (rows wid, wid+16, ...) ----
    for (int j = 0; j < 8; j++) {
        int r = wid + j * 16;
        int v = m0 + r;
        if (v >= N_NODES) break;  // v increases with j; uniform across warp
        float dv = g_dinv[v];
        float acc[4] = {0.f, 0.f, 0.f, 0.f};
        {
            uint2 u = *(const uint2*)(g_xw + (size_t)v * HID + lane * 4);
            h2acc(acc, u.x, dv); h2acc(acc + 2, u.y, dv);
        }
        int s = g_rowptr[v], e = g_rowptr[v + 1];
        int i = s, e4 = s + ((e - s) & ~3);
        for (; i < e4; i += 4) {
            int c0 = __ldg(&g_col[i]),     c1 = __ldg(&g_col[i + 1]);
            int c2 = __ldg(&g_col[i + 2]), c3 = __ldg(&g_col[i + 3]);
            float d0 = __ldg(&g_dinv[c0]), d1 = __ldg(&g_dinv[c1]);
            float d2 = __ldg(&g_dinv[c2]), d3 = __ldg(&g_dinv[c3]);
            uint2 u0 = *(const uint2*)(g_xw + (size_t)c0 * HID + lane * 4);
            uint2 u1 = *(const uint2*)(g_xw + (size_t)c1 * HID + lane * 4);
            uint2 u2 = *(const uint2*)(g_xw + (size_t)c2 * HID + lane * 4);
            uint2 u3 = *(const uint2*)(g_xw + (size_t)c3 * HID + lane * 4);
            h2acc(acc, u0.x, d0); h2acc(acc + 2, u0.y, d0);
            h2acc(acc, u1.x, d1); h2acc(acc + 2, u1.y, d1);
            h2acc(acc, u2.x, d2); h2acc(acc + 2, u2.y, d2);
            h2acc(acc, u3.x, d3); h2acc(acc + 2, u3.y, d3);
        }
        for (; i < e; i++) {
            int c = __ldg(&g_col[i]);
            float d = __ldg(&g_dinv[c]);
            uint2 u = *(const uint2*)(g_xw + (size_t)c * HID + lane * 4);
            h2acc(acc, u.x, d); h2acc(acc + 2, u.y, d);
        }
        float h0 = fmaxf(acc[0] * dv + __ldg(b1 + lane * 4 + 0), 0.f);
        float h1 = fmaxf(acc[1] * dv + __ldg(b1 + lane * 4 + 1), 0.f);
        float h2 = fmaxf(acc[2] * dv + __ldg(b1 + lane * 4 + 2), 0.f);
        float h3 = fmaxf(acc[3] * dv + __ldg(b1 + lane * 4 + 3), 0.f);
        uint2 u;
        *(__half2*)&u.x = __floats2half2_rn(h0, h1);
        *(__half2*)&u.y = __floats2half2_rn(h2, h3);
        *(uint2*)&As[r * PITCH + lane * 4] = u;
    }
    cp_wait<0>();
    __syncthreads();

    // ---- phase 2: 128x64x128 fp16 GEMM from smem ----
    const int wm = (wid & 7) * 16;    // 8 m16 tiles
    const int wn = (wid >> 3) * 32;   // 2 n-halves of 32
    float acc[4][4];
    #pragma unroll
    for (int nt = 0; nt < 4; nt++)
        #pragma unroll
        for (int r = 0; r < 4; r++) acc[nt][r] = 0.f;

    #pragma unroll
    for (int t = 0; t < 8; t++) {
        const int k0 = t * 16;
        uint32_t a[4];
        {
            int row = wm + (lane & 15);
            int col = k0 + ((lane >> 4) & 1) * 8;
            ldsm4(a[0], a[1], a[2], a[3], smem_u32(&As[row * PITCH + col]));
        }
        uint32_t b[4][2];
        #pragma unroll
        for (int np = 0; np < 2; np++) {
            int row = wn + np * 16 + (lane & 7) + (((lane >> 4) & 1) * 8);
            int col = k0 + ((lane >> 3) & 1) * 8;
            uint32_t r0, r1, r2, r3;
            ldsm4(r0, r1, r2, r3, smem_u32(&Bs[row * PITCH + col]));
            b[2 * np][0] = r0;     b[2 * np][1] = r1;
            b[2 * np + 1][0] = r2; b[2 * np + 1][1] = r3;
        }
        #pragma unroll
        for (int nt = 0; nt < 4; nt++)
            mma_f16(acc[nt], a, b[nt]);
    }

    int r0 = m0 + wm + (lane >> 2);
    #pragma unroll
    for (int nt = 0; nt < 4; nt++) {
        int cix = wn + nt * 8 + (lane & 3) * 2;
        if (r0 < N_NODES)
            *(__half2*)&C[(size_t)r0 * OUT_CH + cix] =
                __floats2half2_rn(acc[nt][0], acc[nt][1]);
        if (r0 + 8 < N_NODES)
            *(__half2*)&C[(size_t)(r0 + 8) * OUT_CH + cix] =
                __floats2half2_rn(acc[nt][2], acc[nt][3]);
    }
}

// ---------------- agg2: warp-per-node gather over g_hw (fp16 in, fp32 out) ----------------
__global__ void k_agg2(const float* __restrict__ b2, float* __restrict__ out) {
    int w = (int)((blockIdx.x * (size_t)blockDim.x + threadIdx.x) >> 5);
    if (w >= N_NODES) return;
    int lane = threadIdx.x & 31;

    if (lane == 0) g_cnt[w] = 0;  // restore invariant for next call

    float dv = g_dinv[w];
    float acc[2] = {0.f, 0.f};
    {
        uint32_t u = *(const uint32_t*)(g_hw + (size_t)w * OUT_CH + lane * 2);
        h2acc(acc, u, dv);
    }
    int s = g_rowptr[w], e = g_rowptr[w + 1];
    int i = s, e4 = s + ((e - s) & ~3);
    for (; i < e4; i += 4) {
        int c0 = __ldg(&g_col[i]),     c1 = __ldg(&g_col[i + 1]);
        int c2 = __ldg(&g_col[i + 2]), c3 = __ldg(&g_col[i + 3]);
        float d0 = __ldg(&g_dinv[c0]), d1 = __ldg(&g_dinv[c1]);
        float d2 = __ldg(&g_dinv[c2]), d3 = __ldg(&g_dinv[c3]);
        uint32_t u0 = *(const uint32_t*)(g_hw + (size_t)c0 * OUT_CH + lane * 2);
        uint32_t u1 = *(const uint32_t*)(g_hw + (size_t)c1 * OUT_CH + lane * 2);
        uint32_t u2 = *(const uint32_t*)(g_hw + (size_t)c2 * OUT_CH + lane * 2);
        uint32_t u3 = *(const uint32_t*)(g_hw + (size_t)c3 * OUT_CH + lane * 2);
        h2acc(acc, u0, d0); h2acc(acc, u1, d1);
        h2acc(acc, u2, d2); h2acc(acc, u3, d3);
    }
    for (; i < e; i++) {
        int c = __ldg(&g_col[i]);
        float d = __ldg(&g_dinv[c]);
        uint32_t u = *(const uint32_t*)(g_hw + (size_t)c * OUT_CH + lane * 2);
        h2acc(acc, u, d);
    }
    float r0 = acc[0] * dv + __ldg(b2 + lane * 2 + 0);
    float r1 = acc[1] * dv + __ldg(b2 + lane * 2 + 1);
    *(float2*)(out + (size_t)w * OUT_CH + lane * 2) = make_float2(r0, r1);
}

// ---------------- launch (forked capture: CSR chain || prep+gemm1) ----------------
extern "C" void kernel_launch(void* const* d_in, const int* in_sizes, int n_in,
                              void* d_out, int out_size) {
    const float* x  = (const float*)d_in[0];
    const int*   ei = (const int*)d_in[1];
    const float* W1 = (const float*)d_in[2];
    const float* b1 = (const float*)d_in[3];
    const float* W2 = (const float*)d_in[4];
    const float* b2 = (const float*)d_in[5];
    float* out = (float*)d_out;

    __half *xw, *hw, *wt2h;
    float *wt1;
    cudaGetSymbolAddress((void**)&xw, g_xw);
    cudaGetSymbolAddress((void**)&hw, g_hw);
    cudaGetSymbolAddress((void**)&wt1, g_wt1);
    cudaGetSymbolAddress((void**)&wt2h, g_wt2h);

    const int FUSED_SMEM = (128 + 64) * PITCH * sizeof(__half);  // 52224 B
    cudaFuncSetAttribute(k_fused2, cudaFuncAttributeMaxDynamicSharedMemorySize, FUSED_SMEM);

    cudaStream_t s1;
    cudaEvent_t eFork, eJoin;
    cudaStreamCreateWithFlags(&s1, cudaStreamNonBlocking);
    cudaEventCreateWithFlags(&eFork, cudaEventDisableTiming);
    cudaEventCreateWithFlags(&eJoin, cudaEventDisableTiming);

    // fork
    cudaEventRecord(eFork, 0);
    cudaStreamWaitEvent(s1, eFork, 0);

    // graph-stream (s1): CSR build
    k_hist<<<(N_EDGES + 255) / 256, 256, 0, s1>>>(ei);
    k_scan1<<<NB_SCAN, 1024, 0, s1>>>();
    k_scan23<<<NB_SCAN, 1024, 0, s1>>>();
    k_fill<<<(N_EDGES + 255) / 256, 256, 0, s1>>>(ei);
    cudaEventRecord(eJoin, s1);

    // gemm-stream (default): weights + layer-1 GEMM (graph-independent)
    k_prep_w<<<(IN_CH * HID + 255) / 256, 256>>>(W1, W2);
    k_gemm<HID, IN_CH><<<(N_NODES + 127) / 128, 256>>>(x, wt1, xw, N_NODES);

    // join, then the fused tail
    cudaStreamWaitEvent(0, eJoin, 0);
    k_fused2<<<(N_NODES + 127) / 128, 512, FUSED_SMEM>>>(b1, wt2h, hw);
    k_agg2<<<(N_NODES * 32 + 255) / 256, 256>>>(b2, out);
}

// round 13
// speedup vs baseline: 1.0240x; 1.0240x over previous
#include <cuda_runtime.h>
#include <cuda_fp16.h>
#include <cstdint>
#include <cstddef>

#define N_NODES 100000
#define N_EDGES 1600000
#define IN_CH   256
#define HID     128
#define OUT_CH  64
#define NB_SCAN ((N_NODES + 1023) / 1024)   // 98

// ---------------- scratch (no allocs allowed) ----------------
__device__ int    g_cnt[N_NODES];           // zero at load; re-zeroed by agg2 tail each call
__device__ int    g_rowptr[N_NODES + 1];
__device__ int    g_part[128];
__device__ int    g_col[N_EDGES];
__device__ float  g_dinv[N_NODES];
__device__ float  g_wt1[HID * IN_CH];       // W1^T, tf32-rounded
__device__ __half g_wt2h[OUT_CH * HID];     // W2^T, fp16
__device__ __half g_xw[(size_t)N_NODES * HID];     // x @ W1, fp16
__device__ __half g_h [(size_t)N_NODES * HID];     // relu(layer1), fp16
__device__ __half g_hw[(size_t)N_NODES * OUT_CH];  // h @ W2, fp16

// ---------------- small PTX helpers ----------------
__device__ __forceinline__ uint32_t smem_u32(const void* p) {
    return (uint32_t)__cvta_generic_to_shared(p);
}
__device__ __forceinline__ void cp16(uint32_t dst, const void* src, bool pred) {
    asm volatile("cp.async.cg.shared.global [%0], [%1], 16, %2;"
                 :: "r"(dst), "l"(src), "r"(pred ? 16 : 0));
}
__device__ __forceinline__ void cp_commit() { asm volatile("cp.async.commit_group;"); }
template <int N>
__device__ __forceinline__ void cp_wait() { asm volatile("cp.async.wait_group %0;" :: "n"(N)); }

__device__ __forceinline__ void ldsm4(uint32_t& r0, uint32_t& r1, uint32_t& r2, uint32_t& r3,
                                      uint32_t addr) {
    asm volatile("ldmatrix.sync.aligned.m8n8.x4.b16 {%0,%1,%2,%3}, [%4];"
                 : "=r"(r0), "=r"(r1), "=r"(r2), "=r"(r3) : "r"(addr));
}
__device__ __forceinline__ void mma_tf32(float* c, const uint32_t* a, const uint32_t* b) {
    asm volatile("mma.sync.aligned.m16n8k8.row.col.f32.tf32.tf32.f32 "
                 "{%0,%1,%2,%3}, {%4,%5,%6,%7}, {%8,%9}, {%0,%1,%2,%3};"
                 : "+f"(c[0]), "+f"(c[1]), "+f"(c[2]), "+f"(c[3])
                 : "r"(a[0]), "r"(a[1]), "r"(a[2]), "r"(a[3]), "r"(b[0]), "r"(b[1]));
}
__device__ __forceinline__ void mma_f16(float* c, const uint32_t* a, const uint32_t* b) {
    asm volatile("mma.sync.aligned.m16n8k16.row.col.f32.f16.f16.f32 "
                 "{%0,%1,%2,%3}, {%4,%5,%6,%7}, {%8,%9}, {%0,%1,%2,%3};"
                 : "+f"(c[0]), "+f"(c[1]), "+f"(c[2]), "+f"(c[3])
                 : "r"(a[0]), "r"(a[1]), "r"(a[2]), "r"(a[3]), "r"(b[0]), "r"(b[1]));
}
__device__ __forceinline__ uint32_t to_tf32(uint32_t x) {
    float f = __uint_as_float(x);
    uint32_t o;
    asm("cvt.rna.tf32.f32 %0, %1;" : "=r"(o) : "f"(f));
    return o;
}
__device__ __forceinline__ float round_tf32_f(float f) {
    uint32_t o;
    asm("cvt.rna.tf32.f32 %0, %1;" : "=r"(o) : "f"(f));
    return __uint_as_float(o);
}
__device__ __forceinline__ void h2acc(float* acc, uint32_t u0, float d) {
    float2 f = __half22float2(*(const __half2*)&u0);
    acc[0] += f.x * d; acc[1] += f.y * d;
}

// ---------------- weight transpose/round (gemm-stream) ----------------
__global__ void k_prep_w(const float* __restrict__ W1, const float* __restrict__ W2) {
    int i = blockIdx.x * blockDim.x + threadIdx.x;
    if (i < IN_CH * HID) {             // W1 [256][128] -> Wt1 [128][256], tf32
        int k = i / HID, n = i % HID;
        g_wt1[n * IN_CH + k] = round_tf32_f(W1[i]);
    }
    if (i < HID * OUT_CH) {            // W2 [128][64] -> Wt2h [64][128], fp16
        int k = i / OUT_CH, n = i % OUT_CH;
        g_wt2h[n * HID + k] = __float2half_rn(W2[i]);
    }
}

// ---------------- degree / CSR build (graph-stream) ----------------
// 4 edges per thread via int4 loads of the dst half of edge_index.
__global__ void k_hist(const int* __restrict__ ei) {
    int t = blockIdx.x * blockDim.x + threadIdx.x;
    int e = t * 4;
    if (e < N_EDGES) {  // N_EDGES % 4 == 0, base 16B-aligned
        int4 d = *(const int4*)(ei + N_EDGES + e);
        atomicAdd(&g_cnt[d.x], 1);
        atomicAdd(&g_cnt[d.y], 1);
        atomicAdd(&g_cnt[d.z], 1);
        atomicAdd(&g_cnt[d.w], 1);
    }
}

__global__ void k_scan1() {
    __shared__ int warpsum[32];
    int i = blockIdx.x * 1024 + threadIdx.x;
    int lane = threadIdx.x & 31, wid = threadIdx.x >> 5;
    int c = (i < N_NODES) ? g_cnt[i] : 0;
    if (i < N_NODES) g_dinv[i] = rsqrtf((float)c + 1.0f);  // +1 self loop
    int x = c;
    #pragma unroll
    for (int d = 1; d < 32; d <<= 1) {
        int y = __shfl_up_sync(0xFFFFFFFFu, x, d);
        if (lane >= d) x += y;
    }
    if (lane == 31) warpsum[wid] = x;
    __syncthreads();
    if (wid == 0) {
        int s = warpsum[lane];
        #pragma unroll
        for (int d = 1; d < 32; d <<= 1) {
            int y = __shfl_up_sync(0xFFFFFFFFu, s, d);
            if (lane >= d) s += y;
        }
        warpsum[lane] = s;
    }
    __syncthreads();
    int incl = x + (wid > 0 ? warpsum[wid - 1] : 0);
    if (i < N_NODES) g_rowptr[i + 1] = incl;
    if (threadIdx.x == 1023) g_part[blockIdx.x] = incl;
}

// fused scan2+scan3: every block redundantly scans the 98 partials in smem
__global__ void k_scan23() {
    __shared__ int parts[128];
    int tid = threadIdx.x;
    if (tid < 128) parts[tid] = (tid < NB_SCAN) ? g_part[tid] : 0;
    __syncthreads();
    #pragma unroll
    for (int d = 1; d < 128; d <<= 1) {
        int t = (tid < 128 && tid >= d) ? parts[tid - d] : 0;
        __syncthreads();
        if (tid < 128) parts[tid] += t;
        __syncthreads();
    }
    int base = (blockIdx.x > 0) ? parts[blockIdx.x - 1] : 0;  // exclusive prefix
    int i = blockIdx.x * 1024 + tid;
    if (i < N_NODES) {
        g_rowptr[i + 1] += base;
        g_cnt[i] = 0;  // reset for fill
    }
    if (i == 0) g_rowptr[0] = 0;
}

// 2 edges per thread via int2 loads of both src/dst streams.
__global__ void k_fill(const int* __restrict__ ei) {
    int t = blockIdx.x * blockDim.x + threadIdx.x;
    int e = t * 2;
    if (e < N_EDGES) {  // N_EDGES % 2 == 0, both halves 8B-aligned
        int2 s = *(const int2*)(ei + e);
        int2 d = *(const int2*)(ei + N_EDGES + e);
        int p0 = g_rowptr[d.x] + atomicAdd(&g_cnt[d.x], 1);
        g_col[p0] = s.x;
        int p1 = g_rowptr[d.y] + atomicAdd(&g_cnt[d.y], 1);
        g_col[p1] = s.y;
    }
}

// ---------------- tf32 tensor-core GEMM1: C[M,128] = A[M,256] @ Wt1^T, fp16 out ----------------
template <int BN, int KDIM>
__global__ void __launch_bounds__(256) k_gemm(const float* __restrict__ A,
                                              const float* __restrict__ Wt,
                                              __half* __restrict__ C, int M) {
    constexpr int BM = 128, BK = 16;
    constexpr int NK = KDIM / BK;
    constexpr int LDSW = 20;             // 16 + 4 pad -> conflict-free ldmatrix
    constexpr int N_TILES = BN / 16;
    __shared__ float As[2][BM][LDSW];
    __shared__ float Bs[2][BN][LDSW];

    const int tid = threadIdx.x;
    const int lane = tid & 31, wid = tid >> 5;
    const int wm = (wid & 3) * 32;
    const int wn = (wid >> 2) * (BN / 2);
    const int m0 = blockIdx.x * BM;

    float acc[2][N_TILES][4];
    #pragma unroll
    for (int mt = 0; mt < 2; mt++)
        #pragma unroll
        for (int nt = 0; nt < N_TILES; nt++)
            #pragma unroll
            for (int r = 0; r < 4; r++) acc[mt][nt][r] = 0.f;

    #define LOAD_TILE(T, BUF)                                                        \
    {                                                                                \
        const int k0_ = (T) * BK;                                                    \
        _Pragma("unroll")                                                            \
        for (int l = 0; l < 2; l++) {                                                \
            int q = tid + l * 256;                                                   \
            int row = q >> 2, kq = q & 3;                                            \
            cp16(smem_u32(&As[BUF][row][kq * 4]),                                    \
                 A + (size_t)(m0 + row) * KDIM + k0_ + kq * 4, (m0 + row) < M);      \
        }                                                                            \
        _Pragma("unroll")                                                            \
        for (int l = 0; l < BN / 64; l++) {                                          \
            int q = tid + l * 256;                                                   \
            int n = q >> 2, kq = q & 3;                                              \
            cp16(smem_u32(&Bs[BUF][n][kq * 4]),                                      \
                 Wt + (size_t)n * KDIM + k0_ + kq * 4, true);                        \
        }                                                                            \
        cp_commit();                                                                 \
    }

    LOAD_TILE(0, 0);
    int buf = 0;
    for (int t = 0; t < NK; t++) {
        if (t + 1 < NK) { LOAD_TILE(t + 1, buf ^ 1); cp_wait<1>(); }
        else            { cp_wait<0>(); }
        __syncthreads();

        #pragma unroll
        for (int ks = 0; ks < 2; ks++) {
            const int kb = ks * 8;
            uint32_t a[2][4];
            #pragma unroll
            for (int mt = 0; mt < 2; mt++) {
                int row = wm + mt * 16 + (lane & 15);
                int col = kb + ((lane & 16) >> 2);
                ldsm4(a[mt][0], a[mt][1], a[mt][2], a[mt][3],
                      smem_u32(&As[buf][row][col]));
                #pragma unroll
                for (int r = 0; r < 4; r++) a[mt][r] = to_tf32(a[mt][r]);
            }
            uint32_t b[N_TILES][2];
            #pragma unroll
            for (int np = 0; np < N_TILES / 2; np++) {
                int row = wn + np * 16 + (lane & 7) + ((lane & 16) >> 1);
                int col = kb + ((lane & 8) >> 1);
                uint32_t r0, r1, r2, r3;
                ldsm4(r0, r1, r2, r3, smem_u32(&Bs[buf][row][col]));
                b[2 * np][0] = r0; b[2 * np][1] = r1;
                b[2 * np + 1][0] = r2; b[2 * np + 1][1] = r3;
            }
            #pragma unroll
            for (int mt = 0; mt < 2; mt++)
                #pragma unroll
                for (int nt = 0; nt < N_TILES; nt++)
                    mma_tf32(acc[mt][nt], a[mt], b[nt]);
        }
        __syncthreads();
        buf ^= 1;
    }
    #undef LOAD_TILE

    #pragma unroll
    for (int mt = 0; mt < 2; mt++) {
        int r0 = m0 + wm + mt * 16 + (lane >> 2);
        #pragma unroll
        for (int nt = 0; nt < N_TILES; nt++) {
            int cix = wn + nt * 8 + (lane & 3) * 2;
            if (r0 < M)
                *(__half2*)&C[(size_t)r0 * BN + cix] =
                    __floats2half2_rn(acc[mt][nt][0], acc[mt][nt][1]);
            if (r0 + 8 < M)
                *(__half2*)&C[(size_t)(r0 + 8) * BN + cix] =
                    __floats2half2_rn(acc[mt][nt][2], acc[mt][nt][3]);
        }
    }
}

// ---------------- fp16 GEMM2: C[M,64] = A[M,128](fp16) @ Wt2h^T(fp16), fp16 out ----------------
__global__ void __launch_bounds__(256) k_gemm2h(const __half* __restrict__ A,
                                                const __half* __restrict__ Wt,
                                                __half* __restrict__ C, int M) {
    constexpr int BM = 128, BK = 16;          // k16 per mma step, one step per tile
    constexpr int NK = HID / BK;              // 8
    constexpr int LDS = 24;                   // halves; 48B row stride, conflict-free ldmatrix
    __shared__ __half As[2][BM][LDS];
    __shared__ __half Bs[2][OUT_CH][LDS];

    const int tid = threadIdx.x;
    const int lane = tid & 31, wid = tid >> 5;
    const int wm = (wid & 3) * 32;            // 2 x m16 per warp
    const int wn = (wid >> 2) * 32;           // 4 x n8 per warp
    const int m0 = blockIdx.x * BM;

    float acc[2][4][4];
    #pragma unroll
    for (int mt = 0; mt < 2; mt++)
        #pragma unroll
        for (int nt = 0; nt < 4; nt++)
            #pragma unroll
            for (int r = 0; r < 4; r++) acc[mt][nt][r] = 0.f;

    #define LOAD_TILE2(T, BUF)                                                       \
    {                                                                                \
        const int k0_ = (T) * BK;                                                    \
        {   /* A: 128 rows x 32B = 256 cp16 */                                       \
            int row = tid >> 1, ko = (tid & 1) * 8;                                  \
            cp16(smem_u32(&As[BUF][row][ko]),                                        \
                 A + (size_t)(m0 + row) * HID + k0_ + ko, (m0 + row) < M);           \
        }                                                                            \
        if (tid < 128) { /* B: 64 rows x 32B = 128 cp16 */                           \
            int row = tid >> 1, ko = (tid & 1) * 8;                                  \
            cp16(smem_u32(&Bs[BUF][row][ko]),                                        \
                 Wt + (size_t)row * HID + k0_ + ko, true);                           \
        }                                                                            \
        cp_commit();                                                                 \
    }

    LOAD_TILE2(0, 0);
    int buf = 0;
    for (int t = 0; t < NK; t++) {
        if (t + 1 < NK) { LOAD_TILE2(t + 1, buf ^ 1); cp_wait<1>(); }
        else            { cp_wait<0>(); }
        __syncthreads();

        uint32_t a[2][4];
        #pragma unroll
        for (int mt = 0; mt < 2; mt++) {
            int row = wm + mt * 16 + (lane & 15);
            int col = ((lane >> 4) & 1) * 8;
            ldsm4(a[mt][0], a[mt][1], a[mt][2], a[mt][3], smem_u32(&As[buf][row][col]));
        }
        uint32_t b[4][2];
        #pragma unroll
        for (int np = 0; np < 2; np++) {
            int row = wn + np * 16 + (lane & 7) + (((lane >> 4) & 1) * 8);
            int col = ((lane >> 3) & 1) * 8;
            uint32_t r0, r1, r2, r3;
            ldsm4(r0, r1, r2, r3, smem_u32(&Bs[buf][row][col]));
            b[2 * np][0] = r0;     b[2 * np][1] = r1;
            b[2 * np + 1][0] = r2; b[2 * np + 1][1] = r3;
        }
        #pragma unroll
        for (int mt = 0; mt < 2; mt++)
            #pragma unroll
            for (int nt = 0; nt < 4; nt++)
                mma_f16(acc[mt][nt], a[mt], b[nt]);

        __syncthreads();
        buf ^= 1;
    }
    #undef LOAD_TILE2

    #pragma unroll
    for (int mt = 0; mt < 2; mt++) {
        int r0 = m0 + wm + mt * 16 + (lane >> 2);
        #pragma unroll
        for (int nt = 0; nt < 4; nt++) {
            int cix = wn + nt * 8 + (lane & 3) * 2;
            if (r0 < M)
                *(__half2*)&C[(size_t)r0 * OUT_CH + cix] =
                    __floats2half2_rn(acc[mt][nt][0], acc[mt][nt][1]);
            if (r0 + 8 < M)
                *(__half2*)&C[(size_t)(r0 + 8) * OUT_CH + cix] =
                    __floats2half2_rn(acc[mt][nt][2], acc[mt][nt][3]);
        }
    }
}

// ---------------- warp-per-node aggregation (fp16 in, fp32 accum) ----------------
// out[v] = act( dinv[v] * ( dinv[v]*in[v] + sum_s dinv[s]*in[s] ) + bias )
template <int CH, bool RELU, bool HALF_OUT, bool ZERO_CNT>
__device__ __forceinline__ void agg_core(const __half* __restrict__ in,
                                         const float* __restrict__ bias,
                                         void* __restrict__ out_p) {
    int w = (int)((blockIdx.x * (size_t)blockDim.x + threadIdx.x) >> 5);
    if (w >= N_NODES) return;
    int lane = threadIdx.x & 31;
    constexpr int V = CH / 32;  // halves per lane: 4 (CH=128) or 2 (CH=64)

    if (ZERO_CNT && lane == 0) g_cnt[w] = 0;  // restore invariant for next call

    float dv = g_dinv[w];
    float acc[V] = {};
    {
        const __half* p = in + (size_t)w * CH + lane * V;
        if (V == 4) { uint2 u = *(const uint2*)p; h2acc(acc, u.x, dv); h2acc(acc + 2, u.y, dv); }
        else        { uint32_t u = *(const uint32_t*)p; h2acc(acc, u, dv); }
    }
    int s = g_rowptr[w], e = g_rowptr[w + 1];
    int i = s, e4 = s + ((e - s) & ~3);
    for (; i < e4; i += 4) {
        int c0 = __ldg(&g_col[i]),     c1 = __ldg(&g_col[i + 1]);
        int c2 = __ldg(&g_col[i + 2]), c3 = __ldg(&g_col[i + 3]);
        float d0 = __ldg(&g_dinv[c0]), d1 = __ldg(&g_dinv[c1]);
        float d2 = __ldg(&g_dinv[c2]), d3 = __ldg(&g_dinv[c3]);
        if (V == 4) {
            uint2 u0 = *(const uint2*)(in + (size_t)c0 * CH + lane * 4);
            uint2 u1 = *(const uint2*)(in + (size_t)c1 * CH + lane * 4);
            uint2 u2 = *(const uint2*)(in + (size_t)c2 * CH + lane * 4);
            uint2 u3 = *(const uint2*)(in + (size_t)c3 * CH + lane * 4);
            h2acc(acc, u0.x, d0); h2acc(acc + 2, u0.y, d0);
            h2acc(acc, u1.x, d1); h2acc(acc + 2, u1.y, d1);
            h2acc(acc, u2.x, d2); h2acc(acc + 2, u2.y, d2);
            h2acc(acc, u3.x, d3); h2acc(acc + 2, u3.y, d3);
        } else {
            uint32_t u0 = *(const uint32_t*)(in + (size_t)c0 * CH + lane * 2);
            uint32_t u1 = *(const uint32_t*)(in + (size_t)c1 * CH + lane * 2);
            uint32_t u2 = *(const uint32_t*)(in + (size_t)c2 * CH + lane * 2);
            uint32_t u3 = *(const uint32_t*)(in + (size_t)c3 * CH + lane * 2);
            h2acc(acc, u0, d0); h2acc(acc, u1, d1);
            h2acc(acc, u2, d2); h2acc(acc, u3, d3);
        }
    }
    for (; i < e; i++) {
        int c = __ldg(&g_col[i]);
        float d = __ldg(&g_dinv[c]);
        const __half* p = in + (size_t)c * CH + lane * V;
        if (V == 4) { uint2 u = *(const uint2*)p; h2acc(acc, u.x, d); h2acc(acc + 2, u.y, d); }
        else        { uint32_t u = *(const uint32_t*)p; h2acc(acc, u, d); }
    }
    #pragma unroll
    for (int c = 0; c < V; c++) {
        float r = acc[c] * dv + __ldg(bias + lane * V + c);
        if (RELU) r = fmaxf(r, 0.f);
        acc[c] = r;
    }
    if (HALF_OUT) {
        __half* q = (__half*)out_p + (size_t)w * CH + lane * V;
        if (V == 4) {
            uint2 u;
            *(__half2*)&u.x = __floats2half2_rn(acc[0], acc[1]);
            *(__half2*)&u.y = __floats2half2_rn(acc[2], acc[3]);
            *(uint2*)q = u;
        } else {
            __half2 u = __floats2half2_rn(acc[0], acc[1]);
            *(__half2*)q = u;
        }
    } else {
        float* q = (float*)out_p + (size_t)w * CH + lane * V;
        if (V == 4) *(float4*)q = make_float4(acc[0], acc[1], acc[2], acc[3]);
        else        *(float2*)q = make_float2(acc[0], acc[1]);
    }
}

__global__ void k_agg1(const float* __restrict__ b1) {
    agg_core<HID, true, true, false>(g_xw, b1, g_h);
}
__global__ void k_agg2(const float* __restrict__ b2, float* __restrict__ out) {
    agg_core<OUT_CH, false, false, true>(g_hw, b2, out);
}

// ---------------- launch (forked capture: CSR chain || prep+gemm1) ----------------
extern "C" void kernel_launch(void* const* d_in, const int* in_sizes, int n_in,
                              void* d_out, int out_size) {
    const float* x  = (const float*)d_in[0];
    const int*   ei = (const int*)d_in[1];
    const float* W1 = (const float*)d_in[2];
    const float* b1 = (const float*)d_in[3];
    const float* W2 = (const float*)d_in[4];
    const float* b2 = (const float*)d_in[5];
    float* out = (float*)d_out;

    __half *xw, *h, *hw, *wt2h;
    float *wt1;
    cudaGetSymbolAddress((void**)&xw, g_xw);
    cudaGetSymbolAddress((void**)&h,  g_h);
    cudaGetSymbolAddress((void**)&hw, g_hw);
    cudaGetSymbolAddress((void**)&wt1, g_wt1);
    cudaGetSymbolAddress((void**)&wt2h, g_wt2h);

    cudaStream_t s1;
    cudaEvent_t eFork, eJoin;
    cudaStreamCreateWithFlags(&s1, cudaStreamNonBlocking);
    cudaEventCreateWithFlags(&eFork, cudaEventDisableTiming);
    cudaEventCreateWithFlags(&eJoin, cudaEventDisableTiming);

    // fork
    cudaEventRecord(eFork, 0);
    cudaStreamWaitEvent(s1, eFork, 0);

    // graph-stream (s1): CSR build
    k_hist<<<(N_EDGES / 4 + 255) / 256, 256, 0, s1>>>(ei);
    k_scan1<<<NB_SCAN, 1024, 0, s1>>>();
    k_scan23<<<NB_SCAN, 1024, 0, s1>>>();
    k_fill<<<(N_EDGES / 2 + 255) / 256, 256, 0, s1>>>(ei);
    cudaEventRecord(eJoin, s1);

    // gemm-stream (default): weights + layer-1 GEMM (graph-independent)
    k_prep_w<<<(IN_CH * HID + 255) / 256, 256>>>(W1, W2);
    k_gemm<HID, IN_CH><<<(N_NODES + 127) / 128, 256>>>(x, wt1, xw, N_NODES);

    // join, then the serial tail
    cudaStreamWaitEvent(0, eJoin, 0);
    k_agg1<<<(N_NODES * 32 + 255) / 256, 256>>>(b1);
    k_gemm2h<<<(N_NODES + 127) / 128, 256>>>(h, wt2h, hw, N_NODES);
    k_agg2<<<(N_NODES * 32 + 255) / 256, 256>>>(b2, out);
}

// round 14
// speedup vs baseline: 1.0300x; 1.0058x over previous
#include <cuda_runtime.h>
#include <cuda_fp16.h>
#include <cstdint>
#include <cstddef>

#define N_NODES 100000
#define N_EDGES 1600000
#define IN_CH   256
#define HID     128
#define OUT_CH  64
#define SCAN_ELEMS 8192
#define SCAN_NBLK ((N_NODES + SCAN_ELEMS - 1) / SCAN_ELEMS)  // 13

// ---------------- scratch (no allocs allowed) ----------------
__device__ int    g_cnt[N_NODES];           // zero at load; re-zeroed by k_scan each call
__device__ int    g_rowptr[N_NODES + 1];
__device__ volatile int g_look[SCAN_NBLK];  // lookback flags; re-init to -1 by k_hist
__device__ int    g_col[N_EDGES];
__device__ float  g_dinv[N_NODES];
__device__ float  g_wt1[HID * IN_CH];       // W1^T, tf32-rounded
__device__ __half g_wt2h[OUT_CH * HID];     // W2^T, fp16
__device__ __half g_xw[(size_t)N_NODES * HID];     // x @ W1, fp16
__device__ __half g_h [(size_t)N_NODES * HID];     // relu(layer1), fp16
__device__ __half g_hw[(size_t)N_NODES * OUT_CH];  // h @ W2, fp16

// ---------------- small PTX helpers ----------------
__device__ __forceinline__ uint32_t smem_u32(const void* p) {
    return (uint32_t)__cvta_generic_to_shared(p);
}
__device__ __forceinline__ void cp16(uint32_t dst, const void* src, bool pred) {
    asm volatile("cp.async.cg.shared.global [%0], [%1], 16, %2;"
                 :: "r"(dst), "l"(src), "r"(pred ? 16 : 0));
}
__device__ __forceinline__ void cp_commit() { asm volatile("cp.async.commit_group;"); }
template <int N>
__device__ __forceinline__ void cp_wait() { asm volatile("cp.async.wait_group %0;" :: "n"(N)); }

__device__ __forceinline__ void ldsm4(uint32_t& r0, uint32_t& r1, uint32_t& r2, uint32_t& r3,
                                      uint32_t addr) {
    asm volatile("ldmatrix.sync.aligned.m8n8.x4.b16 {%0,%1,%2,%3}, [%4];"
                 : "=r"(r0), "=r"(r1), "=r"(r2), "=r"(r3) : "r"(addr));
}
__device__ __forceinline__ void mma_tf32(float* c, const uint32_t* a, const uint32_t* b) {
    asm volatile("mma.sync.aligned.m16n8k8.row.col.f32.tf32.tf32.f32 "
                 "{%0,%1,%2,%3}, {%4,%5,%6,%7}, {%8,%9}, {%0,%1,%2,%3};"
                 : "+f"(c[0]), "+f"(c[1]), "+f"(c[2]), "+f"(c[3])
                 : "r"(a[0]), "r"(a[1]), "r"(a[2]), "r"(a[3]), "r"(b[0]), "r"(b[1]));
}
__device__ __forceinline__ void mma_f16(float* c, const uint32_t* a, const uint32_t* b) {
    asm volatile("mma.sync.aligned.m16n8k16.row.col.f32.f16.f16.f32 "
                 "{%0,%1,%2,%3}, {%4,%5,%6,%7}, {%8,%9}, {%0,%1,%2,%3};"
                 : "+f"(c[0]), "+f"(c[1]), "+f"(c[2]), "+f"(c[3])
                 : "r"(a[0]), "r"(a[1]), "r"(a[2]), "r"(a[3]), "r"(b[0]), "r"(b[1]));
}
__device__ __forceinline__ uint32_t to_tf32(uint32_t x) {
    float f = __uint_as_float(x);
    uint32_t o;
    asm("cvt.rna.tf32.f32 %0, %1;" : "=r"(o) : "f"(f));
    return o;
}
__device__ __forceinline__ float round_tf32_f(float f) {
    uint32_t o;
    asm("cvt.rna.tf32.f32 %0, %1;" : "=r"(o) : "f"(f));
    return __uint_as_float(o);
}
__device__ __forceinline__ void h2acc(float* acc, uint32_t u0, float d) {
    float2 f = __half22float2(*(const __half2*)&u0);
    acc[0] += f.x * d; acc[1] += f.y * d;
}

// ---------------- weight transpose/round (gemm-stream) ----------------
__global__ void k_prep_w(const float* __restrict__ W1, const float* __restrict__ W2) {
    int i = blockIdx.x * blockDim.x + threadIdx.x;
    if (i < IN_CH * HID) {             // W1 [256][128] -> Wt1 [128][256], tf32
        int k = i / HID, n = i % HID;
        g_wt1[n * IN_CH + k] = round_tf32_f(W1[i]);
    }
    if (i < HID * OUT_CH) {            // W2 [128][64] -> Wt2h [64][128], fp16
        int k = i / OUT_CH, n = i % OUT_CH;
        g_wt2h[n * HID + k] = __float2half_rn(W2[i]);
    }
}

// ---------------- degree / CSR build (graph-stream) ----------------
// scalar: max thread count = max atomic MLP (R13 lesson: vectorizing these hurt)
__global__ void k_hist(const int* __restrict__ ei) {
    if (blockIdx.x == 0 && threadIdx.x < SCAN_NBLK)
        g_look[threadIdx.x] = -1;      // re-arm lookback flags for this call
    int e = blockIdx.x * blockDim.x + threadIdx.x;
    if (e < N_EDGES) atomicAdd(&g_cnt[ei[N_EDGES + e]], 1);
}

// single-pass scan with chained lookback: 13 blocks, 1024 thr, 8 elems/thr.
// also computes dinv and zeroes cnt for k_fill.
__global__ void k_scan() {
    __shared__ int warpsum[32];
    __shared__ int sprev;
    const int tid = threadIdx.x, lane = tid & 31, wid = tid >> 5;
    const int base = blockIdx.x * SCAN_ELEMS + tid * 8;

    int v[8];
    #pragma unroll
    for (int j = 0; j < 8; j++) {
        int idx = base + j;
        v[j] = (idx < N_NODES) ? g_cnt[idx] : 0;
    }
    #pragma unroll
    for (int j = 0; j < 8; j++) {
        int idx = base + j;
        if (idx < N_NODES) g_dinv[idx] = rsqrtf((float)v[j] + 1.0f);  // +1 self loop
    }
    int run[8], s = 0;
    #pragma unroll
    for (int j = 0; j < 8; j++) { s += v[j]; run[j] = s; }

    int x = s;
    #pragma unroll
    for (int d = 1; d < 32; d <<= 1) {
        int y = __shfl_up_sync(0xFFFFFFFFu, x, d);
        if (lane >= d) x += y;
    }
    if (lane == 31) warpsum[wid] = x;
    __syncthreads();
    if (wid == 0) {
        int t = warpsum[lane];
        #pragma unroll
        for (int d = 1; d < 32; d <<= 1) {
            int y = __shfl_up_sync(0xFFFFFFFFu, t, d);
            if (lane >= d) t += y;
        }
        warpsum[lane] = t;
    }
    __syncthreads();
    int thread_excl = (x - s) + (wid > 0 ? warpsum[wid - 1] : 0);
    int block_total = warpsum[31];

    if (tid == 0) {
        int prev = 0;
        if (blockIdx.x > 0) {
            int t;
            while ((t = g_look[blockIdx.x - 1]) < 0) { }
            prev = t;
        }
        sprev = prev;
        g_look[blockIdx.x] = prev + block_total;  // single-word chain, volatile
    }
    __syncthreads();

    int off = sprev + thread_excl;
    #pragma unroll
    for (int j = 0; j < 8; j++) {
        int idx = base + j;
        if (idx < N_NODES) {
            g_rowptr[idx + 1] = off + run[j];
            g_cnt[idx] = 0;  // reset for k_fill
        }
    }
    if (blockIdx.x == 0 && tid == 0) g_rowptr[0] = 0;
}

__global__ void k_fill(const int* __restrict__ ei) {
    int e = blockIdx.x * blockDim.x + threadIdx.x;
    if (e < N_EDGES) {
        int src = ei[e];
        int dst = ei[N_EDGES + e];
        int pos = g_rowptr[dst] + atomicAdd(&g_cnt[dst], 1);
        g_col[pos] = src;
    }
}

// ---------------- tf32 tensor-core GEMM1: C[M,128] = A[M,256] @ Wt1^T, fp16 out ----------------
template <int BN, int KDIM>
__global__ void __launch_bounds__(256) k_gemm(const float* __restrict__ A,
                                              const float* __restrict__ Wt,
                                              __half* __restrict__ C, int M) {
    constexpr int BM = 128, BK = 16;
    constexpr int NK = KDIM / BK;
    constexpr int LDSW = 20;             // 16 + 4 pad -> conflict-free ldmatrix
    constexpr int N_TILES = BN / 16;
    __shared__ float As[2][BM][LDSW];
    __shared__ float Bs[2][BN][LDSW];

    const int tid = threadIdx.x;
    const int lane = tid & 31, wid = tid >> 5;
    const int wm = (wid & 3) * 32;
    const int wn = (wid >> 2) * (BN / 2);
    const int m0 = blockIdx.x * BM;

    float acc[2][N_TILES][4];
    #pragma unroll
    for (int mt = 0; mt < 2; mt++)
        #pragma unroll
        for (int nt = 0; nt < N_TILES; nt++)
            #pragma unroll
            for (int r = 0; r < 4; r++) acc[mt][nt][r] = 0.f;

    #define LOAD_TILE(T, BUF)                                                        \
    {                                                                                \
        const int k0_ = (T) * BK;                                                    \
        _Pragma("unroll")                                                            \
        for (int l = 0; l < 2; l++) {                                                \
            int q = tid + l * 256;                                                   \
            int row = q >> 2, kq = q & 3;                                            \
            cp16(smem_u32(&As[BUF][row][kq * 4]),                                    \
                 A + (size_t)(m0 + row) * KDIM + k0_ + kq * 4, (m0 + row) < M);      \
        }                                                                            \
        _Pragma("unroll")                                                            \
        for (int l = 0; l < BN / 64; l++) {                                          \
            int q = tid + l * 256;                                                   \
            int n = q >> 2, kq = q & 3;                                              \
            cp16(smem_u32(&Bs[BUF][n][kq * 4]),                                      \
                 Wt + (size_t)n * KDIM + k0_ + kq * 4, true);                        \
        }                                                                            \
        cp_commit();                                                                 \
    }

    LOAD_TILE(0, 0);
    int buf = 0;
    for (int t = 0; t < NK; t++) {
        if (t + 1 < NK) { LOAD_TILE(t + 1, buf ^ 1); cp_wait<1>(); }
        else            { cp_wait<0>(); }
        __syncthreads();

        #pragma unroll
        for (int ks = 0; ks < 2; ks++) {
            const int kb = ks * 8;
            uint32_t a[2][4];
            #pragma unroll
            for (int mt = 0; mt < 2; mt++) {
                int row = wm + mt * 16 + (lane & 15);
                int col = kb + ((lane & 16) >> 2);
                ldsm4(a[mt][0], a[mt][1], a[mt][2], a[mt][3],
                      smem_u32(&As[buf][row][col]));
                #pragma unroll
                for (int r = 0; r < 4; r++) a[mt][r] = to_tf32(a[mt][r]);
            }
            uint32_t b[N_TILES][2];
            #pragma unroll
            for (int np = 0; np < N_TILES / 2; np++) {
                int row = wn + np * 16 + (lane & 7) + ((lane & 16) >> 1);
                int col = kb + ((lane & 8) >> 1);
                uint32_t r0, r1, r2, r3;
                ldsm4(r0, r1, r2, r3, smem_u32(&Bs[buf][row][col]));
                b[2 * np][0] = r0; b[2 * np][1] = r1;
                b[2 * np + 1][0] = r2; b[2 * np + 1][1] = r3;
            }
            #pragma unroll
            for (int mt = 0; mt < 2; mt++)
                #pragma unroll
                for (int nt = 0; nt < N_TILES; nt++)
                    mma_tf32(acc[mt][nt], a[mt], b[nt]);
        }
        __syncthreads();
        buf ^= 1;
    }
    #undef LOAD_TILE

    #pragma unroll
    for (int mt = 0; mt < 2; mt++) {
        int r0 = m0 + wm + mt * 16 + (lane >> 2);
        #pragma unroll
        for (int nt = 0; nt < N_TILES; nt++) {
            int cix = wn + nt * 8 + (lane & 3) * 2;
            if (r0 < M)
                *(__half2*)&C[(size_t)r0 * BN + cix] =
                    __floats2half2_rn(acc[mt][nt][0], acc[mt][nt][1]);
            if (r0 + 8 < M)
                *(__half2*)&C[(size_t)(r0 + 8) * BN + cix] =
                    __floats2half2_rn(acc[mt][nt][2], acc[mt][nt][3]);
        }
    }
}

// ---------------- fp16 GEMM2: C[M,64] = A[M,128](fp16) @ Wt2h^T(fp16), fp16 out ----------------
__global__ void __launch_bounds__(256) k_gemm2h(const __half* __restrict__ A,
                                                const __half* __restrict__ Wt,
                                                __half* __restrict__ C, int M) {
    constexpr int BM = 128, BK = 16;          // k16 per mma step, one step per tile
    constexpr int NK = HID / BK;              // 8
    constexpr int LDS = 24;                   // halves; 48B row stride, conflict-free ldmatrix
    __shared__ __half As[2][BM][LDS];
    __shared__ __half Bs[2][OUT_CH][LDS];

    const int tid = threadIdx.x;
    const int lane = tid & 31, wid = tid >> 5;
    const int wm = (wid & 3) * 32;            // 2 x m16 per warp
    const int wn = (wid >> 2) * 32;           // 4 x n8 per warp
    const int m0 = blockIdx.x * BM;

    float acc[2][4][4];
    #pragma unroll
    for (int mt = 0; mt < 2; mt++)
        #pragma unroll
        for (int nt = 0; nt < 4; nt++)
            #pragma unroll
            for (int r = 0; r < 4; r++) acc[mt][nt][r] = 0.f;

    #define LOAD_TILE2(T, BUF)                                                       \
    {                                                                                \
        const int k0_ = (T) * BK;                                                    \
        {   /* A: 128 rows x 32B = 256 cp16 */                                       \
            int row = tid >> 1, ko = (tid & 1) * 8;                                  \
            cp16(smem_u32(&As[BUF][row][ko]),                                        \
                 A + (size_t)(m0 + row) * HID + k0_ + ko, (m0 + row) < M);           \
        }                                                                            \
        if (tid < 128) { /* B: 64 rows x 32B = 128 cp16 */                           \
            int row = tid >> 1, ko = (tid & 1) * 8;                                  \
            cp16(smem_u32(&Bs[BUF][row][ko]),                                        \
                 Wt + (size_t)row * HID + k0_ + ko, true);                           \
        }                                                                            \
        cp_commit();                                                                 \
    }

    LOAD_TILE2(0, 0);
    int buf = 0;
    for (int t = 0; t < NK; t++) {
        if (t + 1 < NK) { LOAD_TILE2(t + 1, buf ^ 1); cp_wait<1>(); }
        else            { cp_wait<0>(); }
        __syncthreads();

        uint32_t a[2][4];
        #pragma unroll
        for (int mt = 0; mt < 2; mt++) {
            int row = wm + mt * 16 + (lane & 15);
            int col = ((lane >> 4) & 1) * 8;
            ldsm4(a[mt][0], a[mt][1], a[mt][2], a[mt][3], smem_u32(&As[buf][row][col]));
        }
        uint32_t b[4][2];
        #pragma unroll
        for (int np = 0; np < 2; np++) {
            int row = wn + np * 16 + (lane & 7) + (((lane >> 4) & 1) * 8);
            int col = ((lane >> 3) & 1) * 8;
            uint32_t r0, r1, r2, r3;
            ldsm4(r0, r1, r2, r3, smem_u32(&Bs[buf][row][col]));
            b[2 * np][0] = r0;     b[2 * np][1] = r1;
            b[2 * np + 1][0] = r2; b[2 * np + 1][1] = r3;
        }
        #pragma unroll
        for (int mt = 0; mt < 2; mt++)
            #pragma unroll
            for (int nt = 0; nt < 4; nt++)
                mma_f16(acc[mt][nt], a[mt], b[nt]);

        __syncthreads();
        buf ^= 1;
    }
    #undef LOAD_TILE2

    #pragma unroll
    for (int mt = 0; mt < 2; mt++) {
        int r0 = m0 + wm + mt * 16 + (lane >> 2);
        #pragma unroll
        for (int nt = 0; nt < 4; nt++) {
            int cix = wn + nt * 8 + (lane & 3) * 2;
            if (r0 < M)
                *(__half2*)&C[(size_t)r0 * OUT_CH + cix] =
                    __floats2half2_rn(acc[mt][nt][0], acc[mt][nt][1]);
            if (r0 + 8 < M)
                *(__half2*)&C[(size_t)(r0 + 8) * OUT_CH + cix] =
                    __floats2half2_rn(acc[mt][nt][2], acc[mt][nt][3]);
        }
    }
}

// ---------------- warp-per-node aggregation (fp16 in, fp32 accum) ----------------
// out[v] = act( dinv[v] * ( dinv[v]*in[v] + sum_s dinv[s]*in[s] ) + bias )
template <int CH, bool RELU, bool HALF_OUT, bool ZERO_CNT>
__device__ __forceinline__ void agg_core(const __half* __restrict__ in,
                                         const float* __restrict__ bias,
                                         void* __restrict__ out_p) {
    int w = (int)((blockIdx.x * (size_t)blockDim.x + threadIdx.x) >> 5);
    if (w >= N_NODES) return;
    int lane = threadIdx.x & 31;
    constexpr int V = CH / 32;  // halves per lane: 4 (CH=128) or 2 (CH=64)

    if (ZERO_CNT && lane == 0) g_cnt[w] = 0;  // restore invariant for next call

    float dv = g_dinv[w];
    float acc[V] = {};
    {
        const __half* p = in + (size_t)w * CH + lane * V;
        if (V == 4) { uint2 u = *(const uint2*)p; h2acc(acc, u.x, dv); h2acc(acc + 2, u.y, dv); }
        else        { uint32_t u = *(const uint32_t*)p; h2acc(acc, u, dv); }
    }
    int s = g_rowptr[w], e = g_rowptr[w + 1];
    int i = s, e4 = s + ((e - s) & ~3);
    for (; i < e4; i += 4) {
        int c0 = __ldg(&g_col[i]),     c1 = __ldg(&g_col[i + 1]);
        int c2 = __ldg(&g_col[i + 2]), c3 = __ldg(&g_col[i + 3]);
        float d0 = __ldg(&g_dinv[c0]), d1 = __ldg(&g_dinv[c1]);
        float d2 = __ldg(&g_dinv[c2]), d3 = __ldg(&g_dinv[c3]);
        if (V == 4) {
            uint2 u0 = *(const uint2*)(in + (size_t)c0 * CH + lane * 4);
            uint2 u1 = *(const uint2*)(in + (size_t)c1 * CH + lane * 4);
            uint2 u2 = *(const uint2*)(in + (size_t)c2 * CH + lane * 4);
            uint2 u3 = *(const uint2*)(in + (size_t)c3 * CH + lane * 4);
            h2acc(acc, u0.x, d0); h2acc(acc + 2, u0.y, d0);
            h2acc(acc, u1.x, d1); h2acc(acc + 2, u1.y, d1);
            h2acc(acc, u2.x, d2); h2acc(acc + 2, u2.y, d2);
            h2acc(acc, u3.x, d3); h2acc(acc + 2, u3.y, d3);
        } else {
            uint32_t u0 = *(const uint32_t*)(in + (size_t)c0 * CH + lane * 2);
            uint32_t u1 = *(const uint32_t*)(in + (size_t)c1 * CH + lane * 2);
            uint32_t u2 = *(const uint32_t*)(in + (size_t)c2 * CH + lane * 2);
            uint32_t u3 = *(const uint32_t*)(in + (size_t)c3 * CH + lane * 2);
            h2acc(acc, u0, d0); h2acc(acc, u1, d1);
            h2acc(acc, u2, d2); h2acc(acc, u3, d3);
        }
    }
    for (; i < e; i++) {
        int c = __ldg(&g_col[i]);
        float d = __ldg(&g_dinv[c]);
        const __half* p = in + (size_t)c * CH + lane * V;
        if (V == 4) { uint2 u = *(const uint2*)p; h2acc(acc, u.x, d); h2acc(acc + 2, u.y, d); }
        else        { uint32_t u = *(const uint32_t*)p; h2acc(acc, u, d); }
    }
    #pragma unroll
    for (int c = 0; c < V; c++) {
        float r = acc[c] * dv + __ldg(bias + lane * V + c);
        if (RELU) r = fmaxf(r, 0.f);
        acc[c] = r;
    }
    if (HALF_OUT) {
        __half* q = (__half*)out_p + (size_t)w * CH + lane * V;
        if (V == 4) {
            uint2 u;
            *(__half2*)&u.x = __floats2half2_rn(acc[0], acc[1]);
            *(__half2*)&u.y = __floats2half2_rn(acc[2], acc[3]);
            *(uint2*)q = u;
        } else {
            __half2 u = __floats2half2_rn(acc[0], acc[1]);
            *(__half2*)q = u;
        }
    } else {
        float* q = (float*)out_p + (size_t)w * CH + lane * V;
        if (V == 4) *(float4*)q = make_float4(acc[0], acc[1], acc[2], acc[3]);
        else        *(float2*)q = make_float2(acc[0], acc[1]);
    }
}

__global__ void k_agg1(const float* __restrict__ b1) {
    agg_core<HID, true, true, false>(g_xw, b1, g_h);
}
__global__ void k_agg2(const float* __restrict__ b2, float* __restrict__ out) {
    agg_core<OUT_CH, false, false, true>(g_hw, b2, out);
}

// ---------------- launch (forked capture: CSR chain || prep+gemm1) ----------------
extern "C" void kernel_launch(void* const* d_in, const int* in_sizes, int n_in,
                              void* d_out, int out_size) {
    const float* x  = (const float*)d_in[0];
    const int*   ei = (const int*)d_in[1];
    const float* W1 = (const float*)d_in[2];
    const float* b1 = (const float*)d_in[3];
    const float* W2 = (const float*)d_in[4];
    const float* b2 = (const float*)d_in[5];
    float* out = (float*)d_out;

    __half *xw, *h, *hw, *wt2h;
    float *wt1;
    cudaGetSymbolAddress((void**)&xw, g_xw);
    cudaGetSymbolAddress((void**)&h,  g_h);
    cudaGetSymbolAddress((void**)&hw, g_hw);
    cudaGetSymbolAddress((void**)&wt1, g_wt1);
    cudaGetSymbolAddress((void**)&wt2h, g_wt2h);

    cudaStream_t s1;
    cudaEvent_t eFork, eJoin;
    cudaStreamCreateWithFlags(&s1, cudaStreamNonBlocking);
    cudaEventCreateWithFlags(&eFork, cudaEventDisableTiming);
    cudaEventCreateWithFlags(&eJoin, cudaEventDisableTiming);

    // fork
    cudaEventRecord(eFork, 0);
    cudaStreamWaitEvent(s1, eFork, 0);

    // graph-stream (s1): CSR build (3 nodes)
    k_hist<<<(N_EDGES + 255) / 256, 256, 0, s1>>>(ei);
    k_scan<<<SCAN_NBLK, 1024, 0, s1>>>();
    k_fill<<<(N_EDGES + 255) / 256, 256, 0, s1>>>(ei);
    cudaEventRecord(eJoin, s1);

    // gemm-stream (default): weights + layer-1 GEMM (graph-independent)
    k_prep_w<<<(IN_CH * HID + 255) / 256, 256>>>(W1, W2);
    k_gemm<HID, IN_CH><<<(N_NODES + 127) / 128, 256>>>(x, wt1, xw, N_NODES);

    // join, then the serial tail
    cudaStreamWaitEvent(0, eJoin, 0);
    k_agg1<<<(N_NODES * 32 + 255) / 256, 256>>>(b1);
    k_gemm2h<<<(N_NODES + 127) / 128, 256>>>(h, wt2h, hw, N_NODES);
    k_agg2<<<(N_NODES * 32 + 255) / 256, 256>>>(b2, out);
}

// round 15
// speedup vs baseline: 1.0308x; 1.0008x over previous
#include <cuda_runtime.h>
#include <cuda_fp16.h>
#include <cstdint>
#include <cstddef>

#define N_NODES 100000
#define N_EDGES 1600000
#define IN_CH   256
#define HID     128
#define OUT_CH  64
#define SCAN_ELEMS 8192
#define SCAN_NBLK ((N_NODES + SCAN_ELEMS - 1) / SCAN_ELEMS)  // 13

// ---------------- scratch (no allocs allowed) ----------------
__device__ int    g_cnt[N_NODES];           // zero at load; re-zeroed by k_scan each call
__device__ int    g_rowptr[N_NODES + 1];
__device__ volatile int g_look[SCAN_NBLK];  // lookback flags; re-init to -1 by k_hist
__device__ int    g_col[N_EDGES];
__device__ float  g_dinv[N_NODES];
__device__ float  g_wt1[HID * IN_CH];       // W1^T, tf32-rounded
__device__ __half g_wt2h[OUT_CH * HID];     // W2^T, fp16
__device__ __half g_xw[(size_t)N_NODES * HID];     // x @ W1, fp16
__device__ __half g_h [(size_t)N_NODES * HID];     // relu(layer1), fp16
__device__ __half g_hw[(size_t)N_NODES * OUT_CH];  // h @ W2, fp16

// ---------------- small PTX helpers ----------------
__device__ __forceinline__ uint32_t smem_u32(const void* p) {
    return (uint32_t)__cvta_generic_to_shared(p);
}
__device__ __forceinline__ void cp16(uint32_t dst, const void* src, bool pred) {
    asm volatile("cp.async.cg.shared.global [%0], [%1], 16, %2;"
                 :: "r"(dst), "l"(src), "r"(pred ? 16 : 0));
}
__device__ __forceinline__ void cp_commit() { asm volatile("cp.async.commit_group;"); }
template <int N>
__device__ __forceinline__ void cp_wait() { asm volatile("cp.async.wait_group %0;" :: "n"(N)); }

__device__ __forceinline__ void ldsm4(uint32_t& r0, uint32_t& r1, uint32_t& r2, uint32_t& r3,
                                      uint32_t addr) {
    asm volatile("ldmatrix.sync.aligned.m8n8.x4.b16 {%0,%1,%2,%3}, [%4];"
                 : "=r"(r0), "=r"(r1), "=r"(r2), "=r"(r3) : "r"(addr));
}
__device__ __forceinline__ void mma_tf32(float* c, const uint32_t* a, const uint32_t* b) {
    asm volatile("mma.sync.aligned.m16n8k8.row.col.f32.tf32.tf32.f32 "
                 "{%0,%1,%2,%3}, {%4,%5,%6,%7}, {%8,%9}, {%0,%1,%2,%3};"
                 : "+f"(c[0]), "+f"(c[1]), "+f"(c[2]), "+f"(c[3])
                 : "r"(a[0]), "r"(a[1]), "r"(a[2]), "r"(a[3]), "r"(b[0]), "r"(b[1]));
}
__device__ __forceinline__ void mma_f16(float* c, const uint32_t* a, const uint32_t* b) {
    asm volatile("mma.sync.aligned.m16n8k16.row.col.f32.f16.f16.f32 "
                 "{%0,%1,%2,%3}, {%4,%5,%6,%7}, {%8,%9}, {%0,%1,%2,%3};"
                 : "+f"(c[0]), "+f"(c[1]), "+f"(c[2]), "+f"(c[3])
                 : "r"(a[0]), "r"(a[1]), "r"(a[2]), "r"(a[3]), "r"(b[0]), "r"(b[1]));
}
__device__ __forceinline__ uint32_t to_tf32(uint32_t x) {
    float f = __uint_as_float(x);
    uint32_t o;
    asm("cvt.rna.tf32.f32 %0, %1;" : "=r"(o) : "f"(f));
    return o;
}
__device__ __forceinline__ float round_tf32_f(float f) {
    uint32_t o;
    asm("cvt.rna.tf32.f32 %0, %1;" : "=r"(o) : "f"(f));
    return __uint_as_float(o);
}
__device__ __forceinline__ void h2acc(float* acc, uint32_t u0, float d) {
    float2 f = __half22float2(*(const __half2*)&u0);
    acc[0] += f.x * d; acc[1] += f.y * d;
}

// ---------------- weight transpose/round (gemm-stream) ----------------
__global__ void k_prep_w(const float* __restrict__ W1, const float* __restrict__ W2) {
    int i = blockIdx.x * blockDim.x + threadIdx.x;
    if (i < IN_CH * HID) {             // W1 [256][128] -> Wt1 [128][256], tf32
        int k = i / HID, n = i % HID;
        g_wt1[n * IN_CH + k] = round_tf32_f(W1[i]);
    }
    if (i < HID * OUT_CH) {            // W2 [128][64] -> Wt2h [64][128], fp16
        int k = i / OUT_CH, n = i % OUT_CH;
        g_wt2h[n * HID + k] = __float2half_rn(W2[i]);
    }
}

// ---------------- degree / CSR build (graph-stream) ----------------
// scalar: max thread count = max atomic MLP (R13 lesson: vectorizing these hurt)
__global__ void k_hist(const int* __restrict__ ei) {
    if (blockIdx.x == 0 && threadIdx.x < SCAN_NBLK)
        g_look[threadIdx.x] = -1;      // re-arm lookback flags for this call
    int e = blockIdx.x * blockDim.x + threadIdx.x;
    if (e < N_EDGES) atomicAdd(&g_cnt[ei[N_EDGES + e]], 1);
}

// single-pass scan with chained lookback: 13 blocks, 1024 thr, 8 elems/thr.
// also computes dinv and zeroes cnt for k_fill.
__global__ void k_scan() {
    __shared__ int warpsum[32];
    __shared__ int sprev;
    const int tid = threadIdx.x, lane = tid & 31, wid = tid >> 5;
    const int base = blockIdx.x * SCAN_ELEMS + tid * 8;

    int v[8];
    #pragma unroll
    for (int j = 0; j < 8; j++) {
        int idx = base + j;
        v[j] = (idx < N_NODES) ? g_cnt[idx] : 0;
    }
    #pragma unroll
    for (int j = 0; j < 8; j++) {
        int idx = base + j;
        if (idx < N_NODES) g_dinv[idx] = rsqrtf((float)v[j] + 1.0f);  // +1 self loop
    }
    int run[8], s = 0;
    #pragma unroll
    for (int j = 0; j < 8; j++) { s += v[j]; run[j] = s; }

    int x = s;
    #pragma unroll
    for (int d = 1; d < 32; d <<= 1) {
        int y = __shfl_up_sync(0xFFFFFFFFu, x, d);
        if (lane >= d) x += y;
    }
    if (lane == 31) warpsum[wid] = x;
    __syncthreads();
    if (wid == 0) {
        int t = warpsum[lane];
        #pragma unroll
        for (int d = 1; d < 32; d <<= 1) {
            int y = __shfl_up_sync(0xFFFFFFFFu, t, d);
            if (lane >= d) t += y;
        }
        warpsum[lane] = t;
    }
    __syncthreads();
    int thread_excl = (x - s) + (wid > 0 ? warpsum[wid - 1] : 0);
    int block_total = warpsum[31];

    if (tid == 0) {
        int prev = 0;
        if (blockIdx.x > 0) {
            int t;
            while ((t = g_look[blockIdx.x - 1]) < 0) { }
            prev = t;
        }
        sprev = prev;
        g_look[blockIdx.x] = prev + block_total;  // single-word chain, volatile
    }
    __syncthreads();

    int off = sprev + thread_excl;
    #pragma unroll
    for (int j = 0; j < 8; j++) {
        int idx = base + j;
        if (idx < N_NODES) {
            g_rowptr[idx + 1] = off + run[j];
            g_cnt[idx] = 0;  // reset for k_fill
        }
    }
    if (blockIdx.x == 0 && tid == 0) g_rowptr[0] = 0;
}

__global__ void k_fill(const int* __restrict__ ei) {
    int e = blockIdx.x * blockDim.x + threadIdx.x;
    if (e < N_EDGES) {
        int src = ei[e];
        int dst = ei[N_EDGES + e];
        int pos = g_rowptr[dst] + atomicAdd(&g_cnt[dst], 1);
        g_col[pos] = src;
    }
}

// ---------------- tf32 tensor-core GEMM1: C[M,128] = A[M,256] @ Wt1^T, fp16 out ----------------
template <int BN, int KDIM>
__global__ void __launch_bounds__(256) k_gemm(const float* __restrict__ A,
                                              const float* __restrict__ Wt,
                                              __half* __restrict__ C, int M) {
    constexpr int BM = 128, BK = 16;
    constexpr int NK = KDIM / BK;
    constexpr int LDSW = 20;             // 16 + 4 pad -> conflict-free ldmatrix
    constexpr int N_TILES = BN / 16;
    __shared__ float As[2][BM][LDSW];
    __shared__ float Bs[2][BN][LDSW];

    const int tid = threadIdx.x;
    const int lane = tid & 31, wid = tid >> 5;
    const int wm = (wid & 3) * 32;
    const int wn = (wid >> 2) * (BN / 2);
    const int m0 = blockIdx.x * BM;

    float acc[2][N_TILES][4];
    #pragma unroll
    for (int mt = 0; mt < 2; mt++)
        #pragma unroll
        for (int nt = 0; nt < N_TILES; nt++)
            #pragma unroll
            for (int r = 0; r < 4; r++) acc[mt][nt][r] = 0.f;

    #define LOAD_TILE(T, BUF)                                                        \
    {                                                                                \
        const int k0_ = (T) * BK;                                                    \
        _Pragma("unroll")                                                            \
        for (int l = 0; l < 2; l++) {                                                \
            int q = tid + l * 256;                                                   \
            int row = q >> 2, kq = q & 3;                                            \
            cp16(smem_u32(&As[BUF][row][kq * 4]),                                    \
                 A + (size_t)(m0 + row) * KDIM + k0_ + kq * 4, (m0 + row) < M);      \
        }                                                                            \
        _Pragma("unroll")                                                            \
        for (int l = 0; l < BN / 64; l++) {                                          \
            int q = tid + l * 256;                                                   \
            int n = q >> 2, kq = q & 3;                                              \
            cp16(smem_u32(&Bs[BUF][n][kq * 4]),                                      \
                 Wt + (size_t)n * KDIM + k0_ + kq * 4, true);                        \
        }                                                                            \
        cp_commit();                                                                 \
    }

    LOAD_TILE(0, 0);
    int buf = 0;
    for (int t = 0; t < NK; t++) {
        if (t + 1 < NK) { LOAD_TILE(t + 1, buf ^ 1); cp_wait<1>(); }
        else            { cp_wait<0>(); }
        __syncthreads();

        #pragma unroll
        for (int ks = 0; ks < 2; ks++) {
            const int kb = ks * 8;
            uint32_t a[2][4];
            #pragma unroll
            for (int mt = 0; mt < 2; mt++) {
                int row = wm + mt * 16 + (lane & 15);
                int col = kb + ((lane & 16) >> 2);
                ldsm4(a[mt][0], a[mt][1], a[mt][2], a[mt][3],
                      smem_u32(&As[buf][row][col]));
                #pragma unroll
                for (int r = 0; r < 4; r++) a[mt][r] = to_tf32(a[mt][r]);
            }
            uint32_t b[N_TILES][2];
            #pragma unroll
            for (int np = 0; np < N_TILES / 2; np++) {
                int row = wn + np * 16 + (lane & 7) + ((lane & 16) >> 1);
                int col = kb + ((lane & 8) >> 1);
                uint32_t r0, r1, r2, r3;
                ldsm4(r0, r1, r2, r3, smem_u32(&Bs[buf][row][col]));
                b[2 * np][0] = r0; b[2 * np][1] = r1;
                b[2 * np + 1][0] = r2; b[2 * np + 1][1] = r3;
            }
            #pragma unroll
            for (int mt = 0; mt < 2; mt++)
                #pragma unroll
                for (int nt = 0; nt < N_TILES; nt++)
                    mma_tf32(acc[mt][nt], a[mt], b[nt]);
        }
        __syncthreads();
        buf ^= 1;
    }
    #undef LOAD_TILE

    #pragma unroll
    for (int mt = 0; mt < 2; mt++) {
        int r0 = m0 + wm + mt * 16 + (lane >> 2);
        #pragma unroll
        for (int nt = 0; nt < N_TILES; nt++) {
            int cix = wn + nt * 8 + (lane & 3) * 2;
            if (r0 < M)
                *(__half2*)&C[(size_t)r0 * BN + cix] =
                    __floats2half2_rn(acc[mt][nt][0], acc[mt][nt][1]);
            if (r0 + 8 < M)
                *(__half2*)&C[(size_t)(r0 + 8) * BN + cix] =
                    __floats2half2_rn(acc[mt][nt][2], acc[mt][nt][3]);
        }
    }
}

// ---------------- fp16 GEMM2: C[M,64] = A[M,128](fp16) @ Wt2h^T(fp16), fp16 out ----------------
__global__ void __launch_bounds__(256) k_gemm2h(const __half* __restrict__ A,
                                                const __half* __restrict__ Wt,
                                                __half* __restrict__ C, int M) {
    constexpr int BM = 128, BK = 16;          // k16 per mma step, one step per tile
    constexpr int NK = HID / BK;              // 8
    constexpr int LDS = 24;                   // halves; 48B row stride, conflict-free ldmatrix
    __shared__ __half As[2][BM][LDS];
    __shared__ __half Bs[2][OUT_CH][LDS];

    const int tid = threadIdx.x;
    const int lane = tid & 31, wid = tid >> 5;
    const int wm = (wid & 3) * 32;            // 2 x m16 per warp
    const int wn = (wid >> 2) * 32;           // 4 x n8 per warp
    const int m0 = blockIdx.x * BM;

    float acc[2][4][4];
    #pragma unroll
    for (int mt = 0; mt < 2; mt++)
        #pragma unroll
        for (int nt = 0; nt < 4; nt++)
            #pragma unroll
            for (int r = 0; r < 4; r++) acc[mt][nt][r] = 0.f;

    #define LOAD_TILE2(T, BUF)                                                       \
    {                                                                                \
        const int k0_ = (T) * BK;                                                    \
        {   /* A: 128 rows x 32B = 256 cp16 */                                       \
            int row = tid >> 1, ko = (tid & 1) * 8;                                  \
            cp16(smem_u32(&As[BUF][row][ko]),                                        \
                 A + (size_t)(m0 + row) * HID + k0_ + ko, (m0 + row) < M);           \
        }                                                                            \
        if (tid < 128) { /* B: 64 rows x 32B = 128 cp16 */                           \
            int row = tid >> 1, ko = (tid & 1) * 8;                                  \
            cp16(smem_u32(&Bs[BUF][row][ko]),                                        \
                 Wt + (size_t)row * HID + k0_ + ko, true);                           \
        }                                                                            \
        cp_commit();                                                                 \
    }

    LOAD_TILE2(0, 0);
    int buf = 0;
    for (int t = 0; t < NK; t++) {
        if (t + 1 < NK) { LOAD_TILE2(t + 1, buf ^ 1); cp_wait<1>(); }
        else            { cp_wait<0>(); }
        __syncthreads();

        uint32_t a[2][4];
        #pragma unroll
        for (int mt = 0; mt < 2; mt++) {
            int row = wm + mt * 16 + (lane & 15);
            int col = ((lane >> 4) & 1) * 8;
            ldsm4(a[mt][0], a[mt][1], a[mt][2], a[mt][3], smem_u32(&As[buf][row][col]));
        }
        uint32_t b[4][2];
        #pragma unroll
        for (int np = 0; np < 2; np++) {
            int row = wn + np * 16 + (lane & 7) + (((lane >> 4) & 1) * 8);
            int col = ((lane >> 3) & 1) * 8;
            uint32_t r0, r1, r2, r3;
            ldsm4(r0, r1, r2, r3, smem_u32(&Bs[buf][row][col]));
            b[2 * np][0] = r0;     b[2 * np][1] = r1;
            b[2 * np + 1][0] = r2; b[2 * np + 1][1] = r3;
        }
        #pragma unroll
        for (int mt = 0; mt < 2; mt++)
            #pragma unroll
            for (int nt = 0; nt < 4; nt++)
                mma_f16(acc[mt][nt], a[mt], b[nt]);

        __syncthreads();
        buf ^= 1;
    }
    #undef LOAD_TILE2

    #pragma unroll
    for (int mt = 0; mt < 2; mt++) {
        int r0 = m0 + wm + mt * 16 + (lane >> 2);
        #pragma unroll
        for (int nt = 0; nt < 4; nt++) {
            int cix = wn + nt * 8 + (lane & 3) * 2;
            if (r0 < M)
                *(__half2*)&C[(size_t)r0 * OUT_CH + cix] =
                    __floats2half2_rn(acc[mt][nt][0], acc[mt][nt][1]);
            if (r0 + 8 < M)
                *(__half2*)&C[(size_t)(r0 + 8) * OUT_CH + cix] =
                    __floats2half2_rn(acc[mt][nt][2], acc[mt][nt][3]);
        }
    }
}

// ---------------- warp-per-node aggregation (fp16 in, fp32 accum) ----------------
// out[v] = act( dinv[v] * ( dinv[v]*in[v] + sum_s dinv[s]*in[s] ) + bias )
template <int CH, bool RELU, bool HALF_OUT, bool ZERO_CNT>
__device__ __forceinline__ void agg_core(const __half* __restrict__ in,
                                         const float* __restrict__ bias,
                                         void* __restrict__ out_p) {
    int w = (int)((blockIdx.x * (size_t)blockDim.x + threadIdx.x) >> 5);
    if (w >= N_NODES) return;
    int lane = threadIdx.x & 31;
    constexpr int V = CH / 32;  // halves per lane: 4 (CH=128) or 2 (CH=64)

    if (ZERO_CNT && lane == 0) g_cnt[w] = 0;  // restore invariant for next call

    float dv = g_dinv[w];
    float acc[V] = {};
    {
        const __half* p = in + (size_t)w * CH + lane * V;
        if (V == 4) { uint2 u = *(const uint2*)p; h2acc(acc, u.x, dv); h2acc(acc + 2, u.y, dv); }
        else        { uint32_t u = *(const uint32_t*)p; h2acc(acc, u, dv); }
    }
    int s = g_rowptr[w], e = g_rowptr[w + 1];
    int i = s, e4 = s + ((e - s) & ~3);
    for (; i < e4; i += 4) {
        int c0 = __ldg(&g_col[i]),     c1 = __ldg(&g_col[i + 1]);
        int c2 = __ldg(&g_col[i + 2]), c3 = __ldg(&g_col[i + 3]);
        float d0 = __ldg(&g_dinv[c0]), d1 = __ldg(&g_dinv[c1]);
        float d2 = __ldg(&g_dinv[c2]), d3 = __ldg(&g_dinv[c3]);
        if (V == 4) {
            uint2 u0 = *(const uint2*)(in + (size_t)c0 * CH + lane * 4);
            uint2 u1 = *(const uint2*)(in + (size_t)c1 * CH + lane * 4);
            uint2 u2 = *(const uint2*)(in + (size_t)c2 * CH + lane * 4);
            uint2 u3 = *(const uint2*)(in + (size_t)c3 * CH + lane * 4);
            h2acc(acc, u0.x, d0); h2acc(acc + 2, u0.y, d0);
            h2acc(acc, u1.x, d1); h2acc(acc + 2, u1.y, d1);
            h2acc(acc, u2.x, d2); h2acc(acc + 2, u2.y, d2);
            h2acc(acc, u3.x, d3); h2acc(acc + 2, u3.y, d3);
        } else {
            uint32_t u0 = *(const uint32_t*)(in + (size_t)c0 * CH + lane * 2);
            uint32_t u1 = *(const uint32_t*)(in + (size_t)c1 * CH + lane * 2);
            uint32_t u2 = *(const uint32_t*)(in + (size_t)c2 * CH + lane * 2);
            uint32_t u3 = *(const uint32_t*)(in + (size_t)c3 * CH + lane * 2);
            h2acc(acc, u0, d0); h2acc(acc, u1, d1);
            h2acc(acc, u2, d2); h2acc(acc, u3, d3);
        }
    }
    for (; i < e; i++) {
        int c = __ldg(&g_col[i]);
        float d = __ldg(&g_dinv[c]);
        const __half* p = in + (size_t)c * CH + lane * V;
        if (V == 4) { uint2 u = *(const uint2*)p; h2acc(acc, u.x, d); h2acc(acc + 2, u.y, d); }
        else        { uint32_t u = *(const uint32_t*)p; h2acc(acc, u, d); }
    }
    #pragma unroll
    for (int c = 0; c < V; c++) {
        float r = acc[c] * dv + __ldg(bias + lane * V + c);
        if (RELU) r = fmaxf(r, 0.f);
        acc[c] = r;
    }
    if (HALF_OUT) {
        __half* q = (__half*)out_p + (size_t)w * CH + lane * V;
        if (V == 4) {
            uint2 u;
            *(__half2*)&u.x = __floats2half2_rn(acc[0], acc[1]);
            *(__half2*)&u.y = __floats2half2_rn(acc[2], acc[3]);
            *(uint2*)q = u;
        } else {
            __half2 u = __floats2half2_rn(acc[0], acc[1]);
            *(__half2*)q = u;
        }
    } else {
        float* q = (float*)out_p + (size_t)w * CH + lane * V;
        if (V == 4) *(float4*)q = make_float4(acc[0], acc[1], acc[2], acc[3]);
        else        *(float2*)q = make_float2(acc[0], acc[1]);
    }
}

__global__ void k_agg1(const float* __restrict__ b1) {
    agg_core<HID, true, true, false>(g_xw, b1, g_h);
}
__global__ void k_agg2(const float* __restrict__ b2, float* __restrict__ out) {
    agg_core<OUT_CH, false, false, true>(g_hw, b2, out);
}

// ---------------- launch (forked capture: CSR chain || prep+gemm1) ----------------
extern "C" void kernel_launch(void* const* d_in, const int* in_sizes, int n_in,
                              void* d_out, int out_size) {
    const float* x  = (const float*)d_in[0];
    const int*   ei = (const int*)d_in[1];
    const float* W1 = (const float*)d_in[2];
    const float* b1 = (const float*)d_in[3];
    const float* W2 = (const float*)d_in[4];
    const float* b2 = (const float*)d_in[5];
    float* out = (float*)d_out;

    __half *xw, *h, *hw, *wt2h;
    float *wt1;
    cudaGetSymbolAddress((void**)&xw, g_xw);
    cudaGetSymbolAddress((void**)&h,  g_h);
    cudaGetSymbolAddress((void**)&hw, g_hw);
    cudaGetSymbolAddress((void**)&wt1, g_wt1);
    cudaGetSymbolAddress((void**)&wt2h, g_wt2h);

    cudaStream_t s1;
    cudaEvent_t eFork, eJoin;
    cudaStreamCreateWithFlags(&s1, cudaStreamNonBlocking);
    cudaEventCreateWithFlags(&eFork, cudaEventDisableTiming);
    cudaEventCreateWithFlags(&eJoin, cudaEventDisableTiming);

    // fork
    cudaEventRecord(eFork, 0);
    cudaStreamWaitEvent(s1, eFork, 0);

    // graph-stream (s1): CSR build (3 nodes)
    k_hist<<<(N_EDGES + 255) / 256, 256, 0, s1>>>(ei);
    k_scan<<<SCAN_NBLK, 1024, 0, s1>>>();
    k_fill<<<(N_EDGES + 255) / 256, 256, 0, s1>>>(ei);
    cudaEventRecord(eJoin, s1);

    // gemm-stream (default): weights + layer-1 GEMM (graph-independent)
    k_prep_w<<<(IN_CH * HID + 255) / 256, 256>>>(W1, W2);
    k_gemm<HID, IN_CH><<<(N_NODES + 127) / 128, 256>>>(x, wt1, xw, N_NODES);

    // join, then the serial tail
    cudaStreamWaitEvent(0, eJoin, 0);
    k_agg1<<<(N_NODES * 32 + 255) / 256, 256>>>(b1);
    k_gemm2h<<<(N_NODES + 127) / 128, 256>>>(h, wt2h, hw, N_NODES);
    k_agg2<<<(N_NODES * 32 + 255) / 256, 256>>>(b2, out);
}

// round 17
// speedup vs baseline: 1.0690x; 1.0370x over previous
#include <cuda_runtime.h>
#include <cuda_fp16.h>
#include <cstdint>
#include <cstddef>

#define N_NODES 100000
#define N_EDGES 1600000
#define IN_CH   256
#define HID     128
#define OUT_CH  64
#define SCAN_ELEMS 8192
#define SCAN_NBLK ((N_NODES + SCAN_ELEMS - 1) / SCAN_ELEMS)  // 13

// ---------------- scratch (no allocs allowed) ----------------
__device__ int    g_cnt[N_NODES];           // zero at load; re-zeroed by k_agg2 each call
__device__ int    g_rowptr[N_NODES + 1];
__device__ int    g_rowwork[N_NODES];       // working copy of rowptr starts (consumed by fill)
__device__ volatile int g_look[SCAN_NBLK];  // lookback flags; re-init to -1 by k_hist
__device__ int    g_col[N_EDGES];
__device__ float  g_dinv[N_NODES];
__device__ float  g_wt1[HID * IN_CH];       // W1^T, tf32-rounded
__device__ __half g_wt2h[OUT_CH * HID];     // W2^T, fp16
__device__ __half g_xw[(size_t)N_NODES * HID];     // x @ W1, fp16
__device__ __half g_h [(size_t)N_NODES * HID];     // relu(layer1), fp16
__device__ __half g_hw[(size_t)N_NODES * OUT_CH];  // dinv[row] * (h @ W2), fp16 (pre-scaled!)

// ---------------- small PTX helpers ----------------
__device__ __forceinline__ uint32_t smem_u32(const void* p) {
    return (uint32_t)__cvta_generic_to_shared(p);
}
__device__ __forceinline__ void cp16(uint32_t dst, const void* src, bool pred) {
    asm volatile("cp.async.cg.shared.global [%0], [%1], 16, %2;"
                 :: "r"(dst), "l"(src), "r"(pred ? 16 : 0));
}
__device__ __forceinline__ void cp_commit() { asm volatile("cp.async.commit_group;"); }
template <int N>
__device__ __forceinline__ void cp_wait() { asm volatile("cp.async.wait_group %0;" :: "n"(N)); }

__device__ __forceinline__ void ldsm4(uint32_t& r0, uint32_t& r1, uint32_t& r2, uint32_t& r3,
                                      uint32_t addr) {
    asm volatile("ldmatrix.sync.aligned.m8n8.x4.b16 {%0,%1,%2,%3}, [%4];"
                 : "=r"(r0), "=r"(r1), "=r"(r2), "=r"(r3) : "r"(addr));
}
__device__ __forceinline__ void mma_tf32(float* c, const uint32_t* a, const uint32_t* b) {
    asm volatile("mma.sync.aligned.m16n8k8.row.col.f32.tf32.tf32.f32 "
                 "{%0,%1,%2,%3}, {%4,%5,%6,%7}, {%8,%9}, {%0,%1,%2,%3};"
                 : "+f"(c[0]), "+f"(c[1]), "+f"(c[2]), "+f"(c[3])
                 : "r"(a[0]), "r"(a[1]), "r"(a[2]), "r"(a[3]), "r"(b[0]), "r"(b[1]));
}
__device__ __forceinline__ void mma_f16(float* c, const uint32_t* a, const uint32_t* b) {
    asm volatile("mma.sync.aligned.m16n8k16.row.col.f32.f16.f16.f32 "
                 "{%0,%1,%2,%3}, {%4,%5,%6,%7}, {%8,%9}, {%0,%1,%2,%3};"
                 : "+f"(c[0]), "+f"(c[1]), "+f"(c[2]), "+f"(c[3])
                 : "r"(a[0]), "r"(a[1]), "r"(a[2]), "r"(a[3]), "r"(b[0]), "r"(b[1]));
}
__device__ __forceinline__ uint32_t to_tf32(uint32_t x) {
    float f = __uint_as_float(x);
    uint32_t o;
    asm("cvt.rna.tf32.f32 %0, %1;" : "=r"(o) : "f"(f));
    return o;
}
__device__ __forceinline__ float round_tf32_f(float f) {
    uint32_t o;
    asm("cvt.rna.tf32.f32 %0, %1;" : "=r"(o) : "f"(f));
    return __uint_as_float(o);
}
__device__ __forceinline__ void h2acc(float* acc, uint32_t u0, float d) {
    float2 f = __half22float2(*(const __half2*)&u0);
    acc[0] += f.x * d; acc[1] += f.y * d;
}
__device__ __forceinline__ void h2acc1(float* acc, uint32_t u0) {
    float2 f = __half22float2(*(const __half2*)&u0);
    acc[0] += f.x; acc[1] += f.y;
}

// ---------------- weight transpose/round (gemm-stream) ----------------
__global__ void k_prep_w(const float* __restrict__ W1, const float* __restrict__ W2) {
    int i = blockIdx.x * blockDim.x + threadIdx.x;
    if (i < IN_CH * HID) {             // W1 [256][128] -> Wt1 [128][256], tf32
        int k = i / HID, n = i % HID;
        g_wt1[n * IN_CH + k] = round_tf32_f(W1[i]);
    }
    if (i < HID * OUT_CH) {            // W2 [128][64] -> Wt2h [64][128], fp16
        int k = i / OUT_CH, n = i % OUT_CH;
        g_wt2h[n * HID + k] = __float2half_rn(W2[i]);
    }
}

// ---------------- degree / CSR build (graph-stream) ----------------
__global__ void k_hist(const int* __restrict__ ei) {
    if (blockIdx.x == 0 && threadIdx.x < SCAN_NBLK)
        g_look[threadIdx.x] = -1;      // re-arm lookback flags for this call
    int e = blockIdx.x * blockDim.x + threadIdx.x;
    if (e < N_EDGES) atomicAdd(&g_cnt[ei[N_EDGES + e]], 1);
}

// single-pass scan with chained lookback: 13 blocks, 1024 thr, 8 elems/thr.
// also computes dinv, writes rowptr AND the rowwork copy, zeroes cnt.
__global__ void k_scan() {
    __shared__ int warpsum[32];
    __shared__ int sprev;
    const int tid = threadIdx.x, lane = tid & 31, wid = tid >> 5;
    const int base = blockIdx.x * SCAN_ELEMS + tid * 8;

    int v[8];
    #pragma unroll
    for (int j = 0; j < 8; j++) {
        int idx = base + j;
        v[j] = (idx < N_NODES) ? g_cnt[idx] : 0;
    }
    #pragma unroll
    for (int j = 0; j < 8; j++) {
        int idx = base + j;
        if (idx < N_NODES) g_dinv[idx] = rsqrtf((float)v[j] + 1.0f);  // +1 self loop
    }
    int run[8], s = 0;
    #pragma unroll
    for (int j = 0; j < 8; j++) { s += v[j]; run[j] = s; }

    int x = s;
    #pragma unroll
    for (int d = 1; d < 32; d <<= 1) {
        int y = __shfl_up_sync(0xFFFFFFFFu, x, d);
        if (lane >= d) x += y;
    }
    if (lane == 31) warpsum[wid] = x;
    __syncthreads();
    if (wid == 0) {
        int t = warpsum[lane];
        #pragma unroll
        for (int d = 1; d < 32; d <<= 1) {
            int y = __shfl_up_sync(0xFFFFFFFFu, t, d);
            if (lane >= d) t += y;
        }
        warpsum[lane] = t;
    }
    __syncthreads();
    int thread_excl = (x - s) + (wid > 0 ? warpsum[wid - 1] : 0);
    int block_total = warpsum[31];

    if (tid == 0) {
        int prev = 0;
        if (blockIdx.x > 0) {
            int t;
            while ((t = g_look[blockIdx.x - 1]) < 0) { }
            prev = t;
        }
        sprev = prev;
        g_look[blockIdx.x] = prev + block_total;  // single-word chain, volatile
    }
    __syncthreads();

    int off = sprev + thread_excl;
    #pragma unroll
    for (int j = 0; j < 8; j++) {
        int idx = base + j;
        if (idx < N_NODES) {
            int incl = off + run[j];
            g_rowptr[idx + 1] = incl;
            g_rowwork[idx]    = incl - v[j];  // row start, consumed by fill's atomicAdd
            g_cnt[idx] = 0;                    // reset for next call's hist
        }
    }
    if (blockIdx.x == 0 && tid == 0) g_rowptr[0] = 0;
}

// fill via atomicAdd directly on the rowwork copy: no separate rowptr read.
__global__ void k_fill(const int* __restrict__ ei) {
    int e = blockIdx.x * blockDim.x + threadIdx.x;
    if (e < N_EDGES) {
        int src = ei[e];
        int dst = ei[N_EDGES + e];
        int pos = atomicAdd(&g_rowwork[dst], 1);
        g_col[pos] = src;
    }
}

// ---------------- tf32 tensor-core GEMM1: C[M,128] = A[M,256] @ Wt1^T, fp16 out ----------------
template <int BN, int KDIM>
__global__ void __launch_bounds__(256) k_gemm(const float* __restrict__ A,
                                              const float* __restrict__ Wt,
                                              __half* __restrict__ C, int M) {
    constexpr int BM = 128, BK = 16;
    constexpr int NK = KDIM / BK;
    constexpr int LDSW = 20;             // 16 + 4 pad -> conflict-free ldmatrix
    constexpr int N_TILES = BN / 16;
    __shared__ float As[2][BM][LDSW];
    __shared__ float Bs[2][BN][LDSW];

    const int tid = threadIdx.x;
    const int lane = tid & 31, wid = tid >> 5;
    const int wm = (wid & 3) * 32;
    const int wn = (wid >> 2) * (BN / 2);
    const int m0 = blockIdx.x * BM;

    float acc[2][N_TILES][4];
    #pragma unroll
    for (int mt = 0; mt < 2; mt++)
        #pragma unroll
        for (int nt = 0; nt < N_TILES; nt++)
            #pragma unroll
            for (int r = 0; r < 4; r++) acc[mt][nt][r] = 0.f;

    #define LOAD_TILE(T, BUF)                                                        \
    {                                                                                \
        const int k0_ = (T) * BK;                                                    \
        _Pragma("unroll")                                                            \
        for (int l = 0; l < 2; l++) {                                                \
            int q = tid + l * 256;                                                   \
            int row = q >> 2, kq = q & 3;                                            \
            cp16(smem_u32(&As[BUF][row][kq * 4]),                                    \
                 A + (size_t)(m0 + row) * KDIM + k0_ + kq * 4, (m0 + row) < M);      \
        }                                                                            \
        _Pragma("unroll")                                                            \
        for (int l = 0; l < BN / 64; l++) {                                          \
            int q = tid + l * 256;                                                   \
            int n = q >> 2, kq = q & 3;                                              \
            cp16(smem_u32(&Bs[BUF][n][kq * 4]),                                      \
                 Wt + (size_t)n * KDIM + k0_ + kq * 4, true);                        \
        }                                                                            \
        cp_commit();                                                                 \
    }

    LOAD_TILE(0, 0);
    int buf = 0;
    for (int t = 0; t < NK; t++) {
        if (t + 1 < NK) { LOAD_TILE(t + 1, buf ^ 1); cp_wait<1>(); }
        else            { cp_wait<0>(); }
        __syncthreads();

        #pragma unroll
        for (int ks = 0; ks < 2; ks++) {
            const int kb = ks * 8;
            uint32_t a[2][4];
            #pragma unroll
            for (int mt = 0; mt < 2; mt++) {
                int row = wm + mt * 16 + (lane & 15);
                int col = kb + ((lane & 16) >> 2);
                ldsm4(a[mt][0], a[mt][1], a[mt][2], a[mt][3],
                      smem_u32(&As[buf][row][col]));
                #pragma unroll
                for (int r = 0; r < 4; r++) a[mt][r] = to_tf32(a[mt][r]);
            }
            uint32_t b[N_TILES][2];
            #pragma unroll
            for (int np = 0; np < N_TILES / 2; np++) {
                int row = wn + np * 16 + (lane & 7) + ((lane & 16) >> 1);
                int col = kb + ((lane & 8) >> 1);
                uint32_t r0, r1, r2, r3;
                ldsm4(r0, r1, r2, r3, smem_u32(&Bs[buf][row][col]));
                b[2 * np][0] = r0; b[2 * np][1] = r1;
                b[2 * np + 1][0] = r2; b[2 * np + 1][1] = r3;
            }
            #pragma unroll
            for (int mt = 0; mt < 2; mt++)
                #pragma unroll
                for (int nt = 0; nt < N_TILES; nt++)
                    mma_tf32(acc[mt][nt], a[mt], b[nt]);
        }
        __syncthreads();
        buf ^= 1;
    }
    #undef LOAD_TILE

    #pragma unroll
    for (int mt = 0; mt < 2; mt++) {
        int r0 = m0 + wm + mt * 16 + (lane >> 2);
        #pragma unroll
        for (int nt = 0; nt < N_TILES; nt++) {
            int cix = wn + nt * 8 + (lane & 3) * 2;
            if (r0 < M)
                *(__half2*)&C[(size_t)r0 * BN + cix] =
                    __floats2half2_rn(acc[mt][nt][0], acc[mt][nt][1]);
            if (r0 + 8 < M)
                *(__half2*)&C[(size_t)(r0 + 8) * BN + cix] =
                    __floats2half2_rn(acc[mt][nt][2], acc[mt][nt][3]);
        }
    }
}

// ---------------- fp16 GEMM2: C[M,64] = dinv[row] * (A[M,128] @ Wt2h^T), fp16 out ----------------
__global__ void __launch_bounds__(256) k_gemm2h(const __half* __restrict__ A,
                                                const __half* __restrict__ Wt,
                                                __half* __restrict__ C, int M) {
    constexpr int BM = 128, BK = 16;          // k16 per mma step, one step per tile
    constexpr int NK = HID / BK;              // 8
    constexpr int LDS = 24;                   // halves; 48B row stride, conflict-free ldmatrix
    __shared__ __half As[2][BM][LDS];
    __shared__ __half Bs[2][OUT_CH][LDS];

    const int tid = threadIdx.x;
    const int lane = tid & 31, wid = tid >> 5;
    const int wm = (wid & 3) * 32;            // 2 x m16 per warp
    const int wn = (wid >> 2) * 32;           // 4 x n8 per warp
    const int m0 = blockIdx.x * BM;

    float acc[2][4][4];
    #pragma unroll
    for (int mt = 0; mt < 2; mt++)
        #pragma unroll
        for (int nt = 0; nt < 4; nt++)
            #pragma unroll
            for (int r = 0; r < 4; r++) acc[mt][nt][r] = 0.f;

    #define LOAD_TILE2(T, BUF)                                                       \
    {                                                                                \
        const int k0_ = (T) * BK;                                                    \
        {   /* A: 128 rows x 32B = 256 cp16 */                                       \
            int row = tid >> 1, ko = (tid & 1) * 8;                                  \
            cp16(smem_u32(&As[BUF][row][ko]),                                        \
                 A + (size_t)(m0 + row) * HID + k0_ + ko, (m0 + row) < M);           \
        }                                                                            \
        if (tid < 128) { /* B: 64 rows x 32B = 128 cp16 */                           \
            int row = tid >> 1, ko = (tid & 1) * 8;                                  \
            cp16(smem_u32(&Bs[BUF][row][ko]),                                        \
                 Wt + (size_t)row * HID + k0_ + ko, true);                           \
        }                                                                            \
        cp_commit();                                                                 \
    }

    LOAD_TILE2(0, 0);
    int buf = 0;
    for (int t = 0; t < NK; t++) {
        if (t + 1 < NK) { LOAD_TILE2(t + 1, buf ^ 1); cp_wait<1>(); }
        else            { cp_wait<0>(); }
        __syncthreads();

        uint32_t a[2][4];
        #pragma unroll
        for (int mt = 0; mt < 2; mt++) {
            int row = wm + mt * 16 + (lane & 15);
            int col = ((lane >> 4) & 1) * 8;
            ldsm4(a[mt][0], a[mt][1], a[mt][2], a[mt][3], smem_u32(&As[buf][row][col]));
        }
        uint32_t b[4][2];
        #pragma unroll
        for (int np = 0; np < 2; np++) {
            int row = wn + np * 16 + (lane & 7) + (((lane >> 4) & 1) * 8);
            int col = ((lane >> 3) & 1) * 8;
            uint32_t r0, r1, r2, r3;
            ldsm4(r0, r1, r2, r3, smem_u32(&Bs[buf][row][col]));
            b[2 * np][0] = r0;     b[2 * np][1] = r1;
            b[2 * np + 1][0] = r2; b[2 * np + 1][1] = r3;
        }
        #pragma unroll
        for (int mt = 0; mt < 2; mt++)
            #pragma unroll
            for (int nt = 0; nt < 4; nt++)
                mma_f16(acc[mt][nt], a[mt], b[nt]);

        __syncthreads();
        buf ^= 1;
    }
    #undef LOAD_TILE2

    #pragma unroll
    for (int mt = 0; mt < 2; mt++) {
        int r0 = m0 + wm + mt * 16 + (lane >> 2);
        float dv0 = (r0     < M) ? g_dinv[r0]     : 0.f;
        float dv1 = (r0 + 8 < M) ? g_dinv[r0 + 8] : 0.f;
        #pragma unroll
        for (int nt = 0; nt < 4; nt++) {
            int cix = wn + nt * 8 + (lane & 3) * 2;
            if (r0 < M)
                *(__half2*)&C[(size_t)r0 * OUT_CH + cix] =
                    __floats2half2_rn(acc[mt][nt][0] * dv0, acc[mt][nt][1] * dv0);
            if (r0 + 8 < M)
                *(__half2*)&C[(size_t)(r0 + 8) * OUT_CH + cix] =
                    __floats2half2_rn(acc[mt][nt][2] * dv1, acc[mt][nt][3] * dv1);
        }
    }
}

// ---------------- agg1: warp-per-node, per-edge dinv (input NOT pre-scaled) ----------------
__global__ void k_agg1(const float* __restrict__ b1) {
    int w = (int)((blockIdx.x * (size_t)blockDim.x + threadIdx.x) >> 5);
    if (w >= N_NODES) return;
    int lane = threadIdx.x & 31;

    float dv = g_dinv[w];
    float acc[4] = {0.f, 0.f, 0.f, 0.f};
    {
        uint2 u = *(const uint2*)(g_xw + (size_t)w * HID + lane * 4);
        h2acc(acc, u.x, dv); h2acc(acc + 2, u.y, dv);
    }
    int s = g_rowptr[w], e = g_rowptr[w + 1];
    int i = s, e4 = s + ((e - s) & ~3);
    for (; i < e4; i += 4) {
        int c0 = __ldg(&g_col[i]),     c1 = __ldg(&g_col[i + 1]);
        int c2 = __ldg(&g_col[i + 2]), c3 = __ldg(&g_col[i + 3]);
        float d0 = __ldg(&g_dinv[c0]), d1 = __ldg(&g_dinv[c1]);
        float d2 = __ldg(&g_dinv[c2]), d3 = __ldg(&g_dinv[c3]);
        uint2 u0 = *(const uint2*)(g_xw + (size_t)c0 * HID + lane * 4);
        uint2 u1 = *(const uint2*)(g_xw + (size_t)c1 * HID + lane * 4);
        uint2 u2 = *(const uint2*)(g_xw + (size_t)c2 * HID + lane * 4);
        uint2 u3 = *(const uint2*)(g_xw + (size_t)c3 * HID + lane * 4);
        h2acc(acc, u0.x, d0); h2acc(acc + 2, u0.y, d0);
        h2acc(acc, u1.x, d1); h2acc(acc + 2, u1.y, d1);
        h2acc(acc, u2.x, d2); h2acc(acc + 2, u2.y, d2);
        h2acc(acc, u3.x, d3); h2acc(acc + 2, u3.y, d3);
    }
    for (; i < e; i++) {
        int c = __ldg(&g_col[i]);
        float d = __ldg(&g_dinv[c]);
        uint2 u = *(const uint2*)(g_xw + (size_t)c * HID + lane * 4);
        h2acc(acc, u.x, d); h2acc(acc + 2, u.y, d);
    }
    float h0 = fmaxf(acc[0] * dv + __ldg(b1 + lane * 4 + 0), 0.f);
    float h1 = fmaxf(acc[1] * dv + __ldg(b1 + lane * 4 + 1), 0.f);
    float h2 = fmaxf(acc[2] * dv + __ldg(b1 + lane * 4 + 2), 0.f);
    float h3 = fmaxf(acc[3] * dv + __ldg(b1 + lane * 4 + 3), 0.f);
    uint2 u;
    *(__half2*)&u.x = __floats2half2_rn(h0, h1);
    *(__half2*)&u.y = __floats2half2_rn(h2, h3);
    *(uint2*)(g_h + (size_t)w * HID + lane * 4) = u;
}

// ---------------- agg2: input rows pre-scaled by dinv -> no per-edge dinv ----------------
__global__ void k_agg2(const float* __restrict__ b2, float* __restrict__ out) {
    int w = (int)((blockIdx.x * (size_t)blockDim.x + threadIdx.x) >> 5);
    if (w >= N_NODES) return;
    int lane = threadIdx.x & 31;

    if (lane == 0) g_cnt[w] = 0;  // restore invariant for next call's hist

    float acc[2] = {0.f, 0.f};
    {
        uint32_t u = *(const uint32_t*)(g_hw + (size_t)w * OUT_CH + lane * 2);
        h2acc1(acc, u);   // self row already carries dinv[w]
    }
    int s = g_rowptr[w], e = g_rowptr[w + 1];
    int i = s, e4 = s + ((e - s) & ~3);
    for (; i < e4; i += 4) {
        int c0 = __ldg(&g_col[i]),     c1 = __ldg(&g_col[i + 1]);
        int c2 = __ldg(&g_col[i + 2]), c3 = __ldg(&g_col[i + 3]);
        uint32_t u0 = *(const uint32_t*)(g_hw + (size_t)c0 * OUT_CH + lane * 2);
        uint32_t u1 = *(const uint32_t*)(g_hw + (size_t)c1 * OUT_CH + lane * 2);
        uint32_t u2 = *(const uint32_t*)(g_hw + (size_t)c2 * OUT_CH + lane * 2);
        uint32_t u3 = *(const uint32_t*)(g_hw + (size_t)c3 * OUT_CH + lane * 2);
        h2acc1(acc, u0); h2acc1(acc, u1); h2acc1(acc, u2); h2acc1(acc, u3);
    }
    for (; i < e; i++) {
        int c = __ldg(&g_col[i]);
        uint32_t u = *(const uint32_t*)(g_hw + (size_t)c * OUT_CH + lane * 2);
        h2acc1(acc, u);
    }
    float dv = g_dinv[w];
    float r0 = acc[0] * dv + __ldg(b2 + lane * 2 + 0);
    float r1 = acc[1] * dv + __ldg(b2 + lane * 2 + 1);
    *(float2*)(out + (size_t)w * OUT_CH + lane * 2) = make_float2(r0, r1);
}

// ---------------- launch (forked capture: CSR chain || prep+gemm1) ----------------
extern "C" void kernel_launch(void* const* d_in, const int* in_sizes, int n_in,
                              void* d_out, int out_size) {
    const float* x  = (const float*)d_in[0];
    const int*   ei = (const int*)d_in[1];
    const float* W1 = (const float*)d_in[2];
    const float* b1 = (const float*)d_in[3];
    const float* W2 = (const float*)d_in[4];
    const float* b2 = (const float*)d_in[5];
    float* out = (float*)d_out;

    __half *xw, *h, *hw, *wt2h;
    float *wt1;
    cudaGetSymbolAddress((void**)&xw, g_xw);
    cudaGetSymbolAddress((void**)&h,  g_h);
    cudaGetSymbolAddress((void**)&hw, g_hw);
    cudaGetSymbolAddress((void**)&wt1, g_wt1);
    cudaGetSymbolAddress((void**)&wt2h, g_wt2h);

    cudaStream_t s1;
    cudaEvent_t eFork, eJoin;
    cudaStreamCreateWithFlags(&s1, cudaStreamNonBlocking);
    cudaEventCreateWithFlags(&eFork, cudaEventDisableTiming);
    cudaEventCreateWithFlags(&eJoin, cudaEventDisableTiming);

    // fork
    cudaEventRecord(eFork, 0);
    cudaStreamWaitEvent(s1, eFork, 0);

    // graph-stream (s1): CSR build (3 nodes)
    k_hist<<<(N_EDGES + 255) / 256, 256, 0, s1>>>(ei);
    k_scan<<<SCAN_NBLK, 1024, 0, s1>>>();
    k_fill<<<(N_EDGES + 255) / 256, 256, 0, s1>>>(ei);
    cudaEventRecord(eJoin, s1);

    // gemm-stream (default): weights + layer-1 GEMM (graph-independent)
    k_prep_w<<<(IN_CH * HID + 255) / 256, 256>>>(W1, W2);
    k_gemm<HID, IN_CH><<<(N_NODES + 127) / 128, 256>>>(x, wt1, xw, N_NODES);

    // join, then the serial tail
    cudaStreamWaitEvent(0, eJoin, 0);
    k_agg1<<<(N_NODES * 32 + 255) / 256, 256>>>(b1);
    k_gemm2h<<<(N_NODES + 127) / 128, 256>>>(h, wt2h, hw, N_NODES);
    k_agg2<<<(N_NODES * 32 + 255) / 256, 256>>>(b2, out);
}